// round 12
// baseline (speedup 1.0000x reference)
#include <cuda_runtime.h>
#include <cuda_bf16.h>
#include <cuda_fp16.h>
#include <math.h>

#define B 4
#define S 2048
#define D 2048
#define H 16
#define G 4
#define HD 128
#define NQKV 3072   // packed q(2048) | k(512) | v(512)

// ------------------------- scratch (device globals, no allocs) --------------
__device__ __nv_bfloat16 g_xh[(size_t)B * S * D];
__device__ __nv_bfloat16 g_xl[(size_t)B * S * D];
__device__ __nv_bfloat16 g_wqh[(size_t)D * NQKV];          // packed Wqkv hi [k][n]
__device__ __nv_bfloat16 g_wql[(size_t)D * NQKV];
__device__ __half        g_woh[(size_t)H * HD * D];        // Wo*32 (fp16 single)
__device__ __half        g_ah[(size_t)B * S * H * HD];     // attn out (fp16 single)
__device__ float         g_bqkv[NQKV];
__device__ float2        g_rope[(size_t)S * 64];           // (cos,sin) per (s, freq)
// pre-split, roped operands for flash
__device__ __nv_bfloat16 g_qsh[(size_t)B * H * S * HD];
__device__ __nv_bfloat16 g_qsl[(size_t)B * H * S * HD];
__device__ __nv_bfloat16 g_ksh[(size_t)B * G * S * HD];
__device__ __nv_bfloat16 g_ksl[(size_t)B * G * S * HD];
__device__ __half        g_vsh[(size_t)B * G * S * HD];

// ============================ shared PTX helpers =============================
#define LDSM4(R, addr)                                                        \
    asm volatile("ldmatrix.sync.aligned.m8n8.x4.shared.b16 {%0,%1,%2,%3}, [%4];" \
                 : "=r"(R[0]), "=r"(R[1]), "=r"(R[2]), "=r"(R[3]) : "r"(addr))
#define LDSM4T(R, addr)                                                       \
    asm volatile("ldmatrix.sync.aligned.m8n8.x4.trans.shared.b16 {%0,%1,%2,%3}, [%4];" \
                 : "=r"(R[0]), "=r"(R[1]), "=r"(R[2]), "=r"(R[3]) : "r"(addr))
#define MMA16816(d, a, b0v, b1v)                                              \
    asm volatile("mma.sync.aligned.m16n8k16.row.col.f32.bf16.bf16.f32 "       \
                 "{%0,%1,%2,%3},{%4,%5,%6,%7},{%8,%9},{%0,%1,%2,%3};"         \
                 : "+f"(d[0]), "+f"(d[1]), "+f"(d[2]), "+f"(d[3])             \
                 : "r"(a[0]), "r"(a[1]), "r"(a[2]), "r"(a[3]),                \
                   "r"(b0v), "r"(b1v))
#define MMA16816H(d, a, b0v, b1v)                                             \
    asm volatile("mma.sync.aligned.m16n8k16.row.col.f32.f16.f16.f32 "         \
                 "{%0,%1,%2,%3},{%4,%5,%6,%7},{%8,%9},{%0,%1,%2,%3};"         \
                 : "+f"(d[0]), "+f"(d[1]), "+f"(d[2]), "+f"(d[3])             \
                 : "r"(a[0]), "r"(a[1]), "r"(a[2]), "r"(a[3]),                \
                   "r"(b0v), "r"(b1v))
#define CP16(smaddr, gptr)                                                    \
    asm volatile("cp.async.cg.shared.global [%0], [%1], 16;" :: "r"(smaddr), "l"(gptr))
#define CP_COMMIT asm volatile("cp.async.commit_group;")

__device__ __forceinline__ void split2(float x, float y,
                                       unsigned& hi, unsigned& lo) {
    __nv_bfloat16 hx = __float2bfloat16_rn(x);
    __nv_bfloat16 hy = __float2bfloat16_rn(y);
    float rx = x - __bfloat162float(hx);
    float ry = y - __bfloat162float(hy);
    __nv_bfloat16 lx = __float2bfloat16_rn(rx);
    __nv_bfloat16 ly = __float2bfloat16_rn(ry);
    __nv_bfloat162 h2 = __nv_bfloat162(hx, hy);
    __nv_bfloat162 l2 = __nv_bfloat162(lx, ly);
    hi = *(unsigned*)&h2;
    lo = *(unsigned*)&l2;
}

__device__ __forceinline__ unsigned packh2(float x, float y) {
    __half2 h = __floats2half2_rn(x, y);
    return *(unsigned*)&h;
}

// ================= ONE fused conversion / packing / table kernel =============
#define CN0 4194304
#define CN1 1048576
#define CN2 262144
#define CN3 262144
#define CN4 1048576
#define CN5 3072
#define CN6 131072
#define CTOT (CN0 + CN1 + CN2 + CN3 + CN4 + CN5 + CN6)

__global__ void convert_all(const float* __restrict__ x,
                            const float* __restrict__ Wq,
                            const float* __restrict__ Wk,
                            const float* __restrict__ Wv,
                            const float* __restrict__ Wo,
                            const float* __restrict__ bq,
                            const float* __restrict__ bk,
                            const float* __restrict__ bv) {
    long i = (long)blockIdx.x * blockDim.x + threadIdx.x;
    if (i < CN0) {
        float4 v = ((const float4*)x)[i];
        uint2 h, l;
        split2(v.x, v.y, h.x, l.x);
        split2(v.z, v.w, h.y, l.y);
        ((uint2*)g_xh)[i] = h;
        ((uint2*)g_xl)[i] = l;
    } else if (i < CN0 + CN1 + CN2 + CN3) {
        long j;
        int srcN, off;
        const float* src;
        if (i < CN0 + CN1)      { j = i - CN0;               srcN = 2048; off = 0;    src = Wq; }
        else if (i < CN0 + CN1 + CN2) { j = i - CN0 - CN1;   srcN = 512;  off = 2048; src = Wk; }
        else                    { j = i - CN0 - CN1 - CN2;   srcN = 512;  off = 2560; src = Wv; }
        int rw = srcN >> 2;
        int r = (int)(j / rw), c = (int)(j % rw) * 4;
        float4 v = *(const float4*)&src[(size_t)r * srcN + c];
        uint2 h, l;
        split2(v.x, v.y, h.x, l.x);
        split2(v.z, v.w, h.y, l.y);
        size_t d = (size_t)r * NQKV + off + c;
        *(uint2*)&g_wqh[d] = h;
        *(uint2*)&g_wql[d] = l;
    } else if (i < CN0 + CN1 + CN2 + CN3 + CN4) {
        long j = i - (CN0 + CN1 + CN2 + CN3);
        float4 v = ((const float4*)Wo)[j];
        uint2 h;
        h.x = packh2(v.x * 32.0f, v.y * 32.0f);
        h.y = packh2(v.z * 32.0f, v.w * 32.0f);
        ((uint2*)g_woh)[j] = h;
    } else if (i < CN0 + CN1 + CN2 + CN3 + CN4 + CN5) {
        int j = (int)(i - (CN0 + CN1 + CN2 + CN3 + CN4));
        g_bqkv[j] = (j < 2048) ? bq[j] : (j < 2560) ? bk[j - 2048] : bv[j - 2560];
    } else {
        int j = (int)(i - (CN0 + CN1 + CN2 + CN3 + CN4 + CN5));
        int s = j >> 6, f = j & 63;
        float inv_freq = powf(10000.0f, -(float)f / 64.0f);
        float ang = (float)s * inv_freq;
        g_rope[j] = make_float2(cosf(ang), sinf(ang));
    }
}

// ================== wide-tile GEMM constants (128M x 256N) ===================
#define LDA 40
#define LDB2 264          // bf16/fp16 stride for 256-wide B tiles
// QKV stage: Ah/Al 2*128*40*2 = 20480 B ; Bh/Bl 2*32*264*2 = 33792 B
#define QST_B 54272
#define Q_AL 10240
#define Q_BH 20480
#define Q_BL 37376
// out stage: A 128*40*2 = 10240 ; B 32*264*2 = 16896
#define OST_B 27136
#define O_B 10240

// ============= QKV GEMM 128x256 + fused bias/RoPE/split epilogue =============
#define STF2 260   // fp32 stride for 256-wide epilogue tile

__global__ __launch_bounds__(256, 1) void gemm_qkv_fused(
    const __nv_bfloat16* __restrict__ Ahg, const __nv_bfloat16* __restrict__ Alg,
    const __nv_bfloat16* __restrict__ Bhg, const __nv_bfloat16* __restrict__ Blg,
    const float* __restrict__ bias) {
    extern __shared__ __nv_bfloat16 smem[];
    const unsigned smBase = (unsigned)__cvta_generic_to_shared(smem);

    const int tid = threadIdx.x;
    const int lane = tid & 31;
    const int warp = tid >> 5;
    const int wm = (warp >> 2) * 64;       // 0 / 64
    const int wn = (warp & 3) * 64;        // 0/64/128/192
    const int row0 = blockIdx.y * 128;
    const int col0 = blockIdx.x * 256;
    const int K = D, N = NQKV;
    const int NT = K / 32;

    float acc[4][8][4] = {};

    auto issue = [&](int st, int k0) {
        unsigned sb = smBase + st * QST_B;
        #pragma unroll
        for (int j = 0; j < 2; j++) {       // A: 128x32 hi+lo
            int c = tid + j * 256;
            int r = c >> 2, c8 = (c & 3) * 8;
            unsigned so = (unsigned)(r * LDA + c8) * 2;
            CP16(sb + so, &Ahg[(size_t)(row0 + r) * K + k0 + c8]);
            CP16(sb + Q_AL + so, &Alg[(size_t)(row0 + r) * K + k0 + c8]);
        }
        #pragma unroll
        for (int j = 0; j < 4; j++) {       // B: 32x256 hi+lo
            int c = tid + j * 256;
            int r = c >> 5, c8 = (c & 31) * 8;
            unsigned so = (unsigned)(r * LDB2 + c8) * 2;
            CP16(sb + Q_BH + so, &Bhg[(size_t)(k0 + r) * N + col0 + c8]);
            CP16(sb + Q_BL + so, &Blg[(size_t)(k0 + r) * N + col0 + c8]);
        }
    };

    issue(0, 0);
    CP_COMMIT;
    issue(1, 32);
    CP_COMMIT;

    for (int it = 0; it < NT; it++) {
        if (it == NT - 1) {
            asm volatile("cp.async.wait_group 0;");
        } else {
            asm volatile("cp.async.wait_group 1;");
        }
        __syncthreads();
        if (it + 2 < NT) {
            issue((it + 2) % 3, (it + 2) * 32);
            CP_COMMIT;
        }

        unsigned sb = smBase + (it % 3) * QST_B;
        const unsigned aBaseH = sb, aBaseL = sb + Q_AL;
        const unsigned bBaseH = sb + Q_BH, bBaseL = sb + Q_BL;

        #pragma unroll
        for (int ks = 0; ks < 2; ks++) {
            unsigned ah[4][4], al[4][4];
            #pragma unroll
            for (int im = 0; im < 4; im++) {
                unsigned off =
                    ((wm + im * 16 + (lane & 15)) * LDA + ks * 16 + (lane >> 4) * 8) * 2;
                LDSM4(ah[im], aBaseH + off);
                LDSM4(al[im], aBaseL + off);
            }
            int krow = ks * 16 + (lane & 7) + ((lane >> 3) & 1) * 8;
            #pragma unroll
            for (int nb = 0; nb < 4; nb++) {
                unsigned bh[4], bl[4];
                unsigned off = (krow * LDB2 + wn + nb * 16 + (lane >> 4) * 8) * 2;
                LDSM4T(bh, bBaseH + off);
                LDSM4T(bl, bBaseL + off);
                #pragma unroll
                for (int im = 0; im < 4; im++) {
                    MMA16816(acc[im][nb * 2 + 0], ah[im], bh[0], bh[1]);
                    MMA16816(acc[im][nb * 2 + 0], ah[im], bl[0], bl[1]);
                    MMA16816(acc[im][nb * 2 + 0], al[im], bh[0], bh[1]);
                    MMA16816(acc[im][nb * 2 + 1], ah[im], bh[2], bh[3]);
                    MMA16816(acc[im][nb * 2 + 1], ah[im], bl[2], bl[3]);
                    MMA16816(acc[im][nb * 2 + 1], al[im], bh[2], bh[3]);
                }
            }
        }
    }
    __syncthreads();

    // ---- stage full 128x256 fp32 tile (with bias) ----
    float* st = (float*)smem;
    const int qr = lane >> 2, qc = lane & 3;
    #pragma unroll
    for (int im = 0; im < 4; im++) {
        #pragma unroll
        for (int nf = 0; nf < 8; nf++) {
            int rr = wm + im * 16 + qr;
            int cc = wn + nf * 8 + 2 * qc;
            float b0v = bias[col0 + cc], b1v = bias[col0 + cc + 1];
            st[rr * STF2 + cc]           = acc[im][nf][0] + b0v;
            st[rr * STF2 + cc + 1]       = acc[im][nf][1] + b1v;
            st[(rr + 8) * STF2 + cc]     = acc[im][nf][2] + b0v;
            st[(rr + 8) * STF2 + cc + 1] = acc[im][nf][3] + b1v;
        }
    }
    __syncthreads();

    const int bb = row0 >> 11;
    const float scale = 0.08838834764831845f;

    #pragma unroll
    for (int half = 0; half < 2; half++) {
        const int tile = (col0 >> 7) + half;   // 0-15 q, 16-19 k, 20-23 v
        const int ch = half * 128;
        if (tile < 20) {
            bool isq = tile < 16;
            int hh = isq ? tile : tile - 16;
            int nh = isq ? H : G;
            __nv_bfloat16* dh = isq ? g_qsh : g_ksh;
            __nv_bfloat16* dl = isq ? g_qsl : g_ksl;
            float sc = isq ? scale : 1.0f;
            #pragma unroll 4
            for (int t = 0; t < 16; t++) {
                int idx = tid + t * 256;
                int r = idx >> 5;
                int i2 = (idx & 31) * 2;
                int s = (row0 + r) & (S - 1);
                float a0 = st[r * STF2 + ch + i2],      a1 = st[r * STF2 + ch + i2 + 1];
                float c0 = st[r * STF2 + ch + i2 + 64], c1 = st[r * STF2 + ch + i2 + 65];
                float4 tcs = *(const float4*)&g_rope[(size_t)s * 64 + i2];
                float o10 = (a0 * tcs.x - c0 * tcs.y) * sc;
                float o11 = (a1 * tcs.z - c1 * tcs.w) * sc;
                float o20 = (c0 * tcs.x + a0 * tcs.y) * sc;
                float o21 = (c1 * tcs.z + a1 * tcs.w) * sc;
                unsigned h1, l1, h2, l2;
                split2(o10, o11, h1, l1);
                split2(o20, o21, h2, l2);
                size_t dst = ((size_t)(bb * nh + hh) * S + s) * HD + i2;
                *(unsigned*)&dh[dst] = h1;
                *(unsigned*)&dl[dst] = l1;
                *(unsigned*)&dh[dst + 64] = h2;
                *(unsigned*)&dl[dst + 64] = l2;
            }
        } else {
            int gg = tile - 20;
            #pragma unroll 4
            for (int t = 0; t < 32; t++) {
                int idx = tid + t * 256;
                int r = idx >> 6;
                int i2 = (idx & 63) * 2;
                int s = (row0 + r) & (S - 1);
                float v0 = st[r * STF2 + ch + i2], v1 = st[r * STF2 + ch + i2 + 1];
                size_t dst = ((size_t)(bb * G + gg) * S + s) * HD + i2;
                *(unsigned*)&g_vsh[dst] = packh2(v0, v1);
            }
        }
    }
}

// ============== output projection 128x256: fp16 single x single ==============
__global__ __launch_bounds__(256, 1) void gemm_out_h(
    const __half* __restrict__ Ag, const __half* __restrict__ Bg,
    const float* __restrict__ bias, float* __restrict__ C,
    int M, int N, int K) {
    extern __shared__ __nv_bfloat16 smemb[];
    __half* smem = (__half*)smemb;
    const unsigned smBase = (unsigned)__cvta_generic_to_shared(smem);

    const int tid = threadIdx.x;
    const int lane = tid & 31;
    const int warp = tid >> 5;
    const int wm = (warp >> 2) * 64;
    const int wn = (warp & 3) * 64;
    const int row0 = blockIdx.y * 128;
    const int col0 = blockIdx.x * 256;
    const int NT = K / 32;

    float acc[4][8][4] = {};

    auto issue = [&](int st, int k0) {
        unsigned sb = smBase + st * OST_B;
        #pragma unroll
        for (int j = 0; j < 2; j++) {
            int c = tid + j * 256;
            int r = c >> 2, c8 = (c & 3) * 8;
            unsigned so = (unsigned)(r * LDA + c8) * 2;
            CP16(sb + so, &Ag[(size_t)(row0 + r) * K + k0 + c8]);
        }
        #pragma unroll
        for (int j = 0; j < 4; j++) {
            int c = tid + j * 256;
            int r = c >> 5, c8 = (c & 31) * 8;
            unsigned so = (unsigned)(r * LDB2 + c8) * 2;
            CP16(sb + O_B + so, &Bg[(size_t)(k0 + r) * N + col0 + c8]);
        }
    };

    issue(0, 0);
    CP_COMMIT;
    issue(1, 32);
    CP_COMMIT;

    for (int it = 0; it < NT; it++) {
        if (it == NT - 1) {
            asm volatile("cp.async.wait_group 0;");
        } else {
            asm volatile("cp.async.wait_group 1;");
        }
        __syncthreads();
        if (it + 2 < NT) {
            issue((it + 2) % 3, (it + 2) * 32);
            CP_COMMIT;
        }

        unsigned sb = smBase + (it % 3) * OST_B;
        const unsigned aBase = sb;
        const unsigned bBase = sb + O_B;

        #pragma unroll
        for (int ks = 0; ks < 2; ks++) {
            unsigned ah[4][4];
            #pragma unroll
            for (int im = 0; im < 4; im++) {
                unsigned off =
                    ((wm + im * 16 + (lane & 15)) * LDA + ks * 16 + (lane >> 4) * 8) * 2;
                LDSM4(ah[im], aBase + off);
            }
            int krow = ks * 16 + (lane & 7) + ((lane >> 3) & 1) * 8;
            #pragma unroll
            for (int nb = 0; nb < 4; nb++) {
                unsigned bh[4];
                unsigned off = (krow * LDB2 + wn + nb * 16 + (lane >> 4) * 8) * 2;
                LDSM4T(bh, bBase + off);
                #pragma unroll
                for (int im = 0; im < 4; im++) {
                    MMA16816H(acc[im][nb * 2 + 0], ah[im], bh[0], bh[1]);
                    MMA16816H(acc[im][nb * 2 + 1], ah[im], bh[2], bh[3]);
                }
            }
        }
    }

    const float inv32 = 1.0f / 32.0f;
    const int qr = lane >> 2, qc = lane & 3;
    #pragma unroll
    for (int im = 0; im < 4; im++) {
        #pragma unroll
        for (int nf = 0; nf < 8; nf++) {
            int row = row0 + wm + im * 16 + qr;
            int col = col0 + wn + nf * 8 + 2 * qc;
            float b0v = bias[col], b1v = bias[col + 1];
            float2 o0 = make_float2(acc[im][nf][0] * inv32 + b0v,
                                    acc[im][nf][1] * inv32 + b1v);
            float2 o1 = make_float2(acc[im][nf][2] * inv32 + b0v,
                                    acc[im][nf][3] * inv32 + b1v);
            *(float2*)&C[(size_t)row * N + col] = o0;
            *(float2*)&C[(size_t)(row + 8) * N + col] = o1;
        }
    }
}

// ====== Flash attention: 128-row q tiles, QK bf16 3-term, PV fp16 1-term =====
#define LQ 136

__global__ __launch_bounds__(256) void flash_tc() {
    extern __shared__ __nv_bfloat16 smb[];
    __nv_bfloat16* Qh = smb;
    __nv_bfloat16* Ql = Qh + 128 * LQ;
    __nv_bfloat16* Kh = Ql + 128 * LQ;
    __nv_bfloat16* Kl = Kh + 64 * LQ;
    __half*        Vh = (__half*)(Kl + 64 * LQ);

    const int tid  = threadIdx.x;
    const int lane = tid & 31;
    const int warp = tid >> 5;
    const int qtile = gridDim.z - 1 - blockIdx.z;
    const int h  = blockIdx.x;
    const int b  = blockIdx.y;
    const int g  = h / (H / G);
    const int q0 = qtile * 128;
    const int wm = warp * 16;

    const unsigned qBH = (unsigned)__cvta_generic_to_shared(Qh);
    const unsigned qBL = (unsigned)__cvta_generic_to_shared(Ql);
    const unsigned kBH = (unsigned)__cvta_generic_to_shared(Kh);
    const unsigned kBL = (unsigned)__cvta_generic_to_shared(Kl);
    const unsigned vBH = (unsigned)__cvta_generic_to_shared(Vh);

    #pragma unroll
    for (int it = 0; it < 8; it++) {
        int i4 = tid + it * 256;
        int r  = i4 >> 4;
        int c8 = (i4 & 15) * 8;
        size_t gi = ((size_t)(b * H + h) * S + q0 + r) * HD + c8;
        *(uint4*)&Qh[r * LQ + c8] = *(const uint4*)&g_qsh[gi];
        *(uint4*)&Ql[r * LQ + c8] = *(const uint4*)&g_qsl[gi];
    }

    const int gid = lane >> 2, tig = lane & 3;
    const int row0g = q0 + wm + gid;
    const int row1g = row0g + 8;
    const int wmaxrow = q0 + wm + 15;

    float rm0 = -1e30f, rm1 = -1e30f, rl0 = 0.0f, rl1 = 0.0f;
    float oacc[16][4] = {};

    const int NKT = 2 * qtile + 2;
    for (int kt = 0; kt < NKT; kt++) {
        const int k0 = kt * 64;
        __syncthreads();
        #pragma unroll
        for (int it = 0; it < 4; it++) {
            int i4 = tid + it * 256;
            int r  = i4 >> 4;
            int c8 = (i4 & 15) * 8;
            size_t gi = ((size_t)(b * G + g) * S + k0 + r) * HD + c8;
            unsigned so = r * LQ + c8;
            *(uint4*)&Kh[so] = *(const uint4*)&g_ksh[gi];
            *(uint4*)&Kl[so] = *(const uint4*)&g_ksl[gi];
            *(uint4*)&Vh[so] = *(const uint4*)&g_vsh[gi];
        }
        __syncthreads();

        if (k0 > wmaxrow) continue;

        float sacc[8][4] = {};
        #pragma unroll
        for (int ks = 0; ks < 8; ks++) {
            unsigned ah[4], al[4];
            unsigned offa = ((wm + (lane & 15)) * LQ + ks * 16 + (lane >> 4) * 8) * 2;
            LDSM4(ah, qBH + offa);
            LDSM4(al, qBL + offa);
            #pragma unroll
            for (int nb = 0; nb < 4; nb++) {
                unsigned kh[4], kl[4];
                unsigned offb = ((nb * 16 + (lane >> 4) * 8 + (lane & 7)) * LQ +
                                 ks * 16 + ((lane >> 3) & 1) * 8) * 2;
                LDSM4(kh, kBH + offb);
                LDSM4(kl, kBL + offb);
                MMA16816(sacc[2 * nb + 0], ah, kh[0], kh[1]);
                MMA16816(sacc[2 * nb + 0], ah, kl[0], kl[1]);
                MMA16816(sacc[2 * nb + 0], al, kh[0], kh[1]);
                MMA16816(sacc[2 * nb + 1], ah, kh[2], kh[3]);
                MMA16816(sacc[2 * nb + 1], ah, kl[2], kl[3]);
                MMA16816(sacc[2 * nb + 1], al, kh[2], kh[3]);
            }
        }

        if (k0 + 63 > row0g) {
            #pragma unroll
            for (int nt = 0; nt < 8; nt++) {
                int colg = k0 + nt * 8 + 2 * tig;
                if (colg > row0g)     sacc[nt][0] = -1e30f;
                if (colg + 1 > row0g) sacc[nt][1] = -1e30f;
                if (colg > row1g)     sacc[nt][2] = -1e30f;
                if (colg + 1 > row1g) sacc[nt][3] = -1e30f;
            }
        }

        float mx0 = rm0, mx1 = rm1;
        #pragma unroll
        for (int nt = 0; nt < 8; nt++) {
            mx0 = fmaxf(mx0, fmaxf(sacc[nt][0], sacc[nt][1]));
            mx1 = fmaxf(mx1, fmaxf(sacc[nt][2], sacc[nt][3]));
        }
        mx0 = fmaxf(mx0, __shfl_xor_sync(0xffffffff, mx0, 1));
        mx0 = fmaxf(mx0, __shfl_xor_sync(0xffffffff, mx0, 2));
        mx1 = fmaxf(mx1, __shfl_xor_sync(0xffffffff, mx1, 1));
        mx1 = fmaxf(mx1, __shfl_xor_sync(0xffffffff, mx1, 2));
        float sc0 = __expf(rm0 - mx0);
        float sc1 = __expf(rm1 - mx1);
        rm0 = mx0; rm1 = mx1;
        float sum0 = 0.0f, sum1 = 0.0f;
        #pragma unroll
        for (int nt = 0; nt < 8; nt++) {
            sacc[nt][0] = __expf(sacc[nt][0] - mx0);
            sacc[nt][1] = __expf(sacc[nt][1] - mx0);
            sacc[nt][2] = __expf(sacc[nt][2] - mx1);
            sacc[nt][3] = __expf(sacc[nt][3] - mx1);
            sum0 += sacc[nt][0] + sacc[nt][1];
            sum1 += sacc[nt][2] + sacc[nt][3];
        }
        sum0 += __shfl_xor_sync(0xffffffff, sum0, 1);
        sum0 += __shfl_xor_sync(0xffffffff, sum0, 2);
        sum1 += __shfl_xor_sync(0xffffffff, sum1, 1);
        sum1 += __shfl_xor_sync(0xffffffff, sum1, 2);
        rl0 = rl0 * sc0 + sum0;
        rl1 = rl1 * sc1 + sum1;
        #pragma unroll
        for (int nt = 0; nt < 16; nt++) {
            oacc[nt][0] *= sc0; oacc[nt][1] *= sc0;
            oacc[nt][2] *= sc1; oacc[nt][3] *= sc1;
        }

        #pragma unroll
        for (int j = 0; j < 4; j++) {
            unsigned ph[4];
            ph[0] = packh2(sacc[2 * j][0],     sacc[2 * j][1]);
            ph[1] = packh2(sacc[2 * j][2],     sacc[2 * j][3]);
            ph[2] = packh2(sacc[2 * j + 1][0], sacc[2 * j + 1][1]);
            ph[3] = packh2(sacc[2 * j + 1][2], sacc[2 * j + 1][3]);
            #pragma unroll
            for (int nb = 0; nb < 8; nb++) {
                unsigned vh4[4];
                unsigned offv = ((j * 16 + (lane & 7) + ((lane >> 3) & 1) * 8) * LQ +
                                 nb * 16 + (lane >> 4) * 8) * 2;
                LDSM4T(vh4, vBH + offv);
                MMA16816H(oacc[2 * nb + 0], ph, vh4[0], vh4[1]);
                MMA16816H(oacc[2 * nb + 1], ph, vh4[2], vh4[3]);
            }
        }
    }

    float li0 = 1.0f / rl0, li1 = 1.0f / rl1;
    size_t or0 = (size_t)(b * S + row0g) * (H * HD) + h * HD;
    size_t or1 = (size_t)(b * S + row1g) * (H * HD) + h * HD;
    #pragma unroll
    for (int nt = 0; nt < 16; nt++) {
        int col = nt * 8 + 2 * tig;
        *(unsigned*)&g_ah[or0 + col] = packh2(oacc[nt][0] * li0, oacc[nt][1] * li0);
        *(unsigned*)&g_ah[or1 + col] = packh2(oacc[nt][2] * li1, oacc[nt][3] * li1);
    }
}

// =============================== launch ======================================
extern "C" void kernel_launch(void* const* d_in, const int* in_sizes, int n_in,
                              void* d_out, int out_size) {
    const float* x  = (const float*)d_in[0];
    const float* Wq = (const float*)d_in[1];
    const float* bq = (const float*)d_in[2];
    const float* Wk = (const float*)d_in[3];
    const float* bk = (const float*)d_in[4];
    const float* Wv = (const float*)d_in[5];
    const float* bv = (const float*)d_in[6];
    const float* Wo = (const float*)d_in[7];
    const float* bo = (const float*)d_in[8];
    float* out = (float*)d_out;

    __nv_bfloat16 *xh, *xl, *wqh, *wql;
    __half *woh, *ah;
    float *bqkv;
    cudaGetSymbolAddress((void**)&xh, g_xh);
    cudaGetSymbolAddress((void**)&xl, g_xl);
    cudaGetSymbolAddress((void**)&wqh, g_wqh);
    cudaGetSymbolAddress((void**)&wql, g_wql);
    cudaGetSymbolAddress((void**)&woh, g_woh);
    cudaGetSymbolAddress((void**)&ah, g_ah);
    cudaGetSymbolAddress((void**)&bqkv, g_bqkv);

    const int M = B * S;  // 8192

    convert_all<<<(CTOT + 255) / 256, 256>>>(x, Wq, Wk, Wv, Wo, bq, bk, bv);

    size_t gsm = (size_t)3 * QST_B;                 // 162816 B (covers 133120 epi)
    cudaFuncSetAttribute(gemm_qkv_fused, cudaFuncAttributeMaxDynamicSharedMemorySize, (int)gsm);
    size_t gsmh = (size_t)3 * OST_B;                // 81408 B
    cudaFuncSetAttribute(gemm_out_h, cudaFuncAttributeMaxDynamicSharedMemorySize, (int)gsmh);

    // ---- fused QKV projection + bias + RoPE + split (128x256 tiles) ----
    gemm_qkv_fused<<<dim3(NQKV / 256, M / 128), 256, gsm>>>(xh, xl, wqh, wql, bqkv);

    // ---- flash attention ----
    size_t smem = (size_t)(2 * 128 + 3 * 64) * LQ * sizeof(__nv_bfloat16);  // 121856 B
    cudaFuncSetAttribute(flash_tc, cudaFuncAttributeMaxDynamicSharedMemorySize, (int)smem);
    flash_tc<<<dim3(H, B, S / 128), 256, smem>>>();

    // ---- output projection (128x256 tiles) ----
    gemm_out_h<<<dim3(D / 256, M / 128), 256, gsmh>>>(
        ah, woh, bo, out, M, D, H * HD);
}

// round 13
// speedup vs baseline: 1.1248x; 1.1248x over previous
#include <cuda_runtime.h>
#include <cuda_bf16.h>
#include <cuda_fp16.h>
#include <math.h>

#define B 4
#define S 2048
#define D 2048
#define H 16
#define G 4
#define HD 128
#define NQKV 3072   // packed q(2048) | k(512) | v(512)

// ------------------------- scratch (device globals, no allocs) --------------
__device__ __nv_bfloat16 g_xh[(size_t)B * S * D];
__device__ __nv_bfloat16 g_xl[(size_t)B * S * D];
__device__ __nv_bfloat16 g_wqh[(size_t)D * NQKV];          // packed Wqkv hi [k][n]
__device__ __nv_bfloat16 g_wql[(size_t)D * NQKV];
__device__ __half        g_woh[(size_t)H * HD * D];        // Wo*32 (fp16 single)
__device__ __half        g_ah[(size_t)B * S * H * HD];     // attn out (fp16 single)
__device__ float         g_bqkv[NQKV];
__device__ float2        g_rope[(size_t)S * 64];           // (cos,sin) per (s, freq)
// pre-split, roped operands for flash
__device__ __nv_bfloat16 g_qsh[(size_t)B * H * S * HD];
__device__ __nv_bfloat16 g_qsl[(size_t)B * H * S * HD];
__device__ __nv_bfloat16 g_ksh[(size_t)B * G * S * HD];
__device__ __nv_bfloat16 g_ksl[(size_t)B * G * S * HD];
__device__ __half        g_vsh[(size_t)B * G * S * HD];

// ============================ shared PTX helpers =============================
#define LDSM4(R, addr)                                                        \
    asm volatile("ldmatrix.sync.aligned.m8n8.x4.shared.b16 {%0,%1,%2,%3}, [%4];" \
                 : "=r"(R[0]), "=r"(R[1]), "=r"(R[2]), "=r"(R[3]) : "r"(addr))
#define LDSM4T(R, addr)                                                       \
    asm volatile("ldmatrix.sync.aligned.m8n8.x4.trans.shared.b16 {%0,%1,%2,%3}, [%4];" \
                 : "=r"(R[0]), "=r"(R[1]), "=r"(R[2]), "=r"(R[3]) : "r"(addr))
#define MMA16816(d, a, b0v, b1v)                                              \
    asm volatile("mma.sync.aligned.m16n8k16.row.col.f32.bf16.bf16.f32 "       \
                 "{%0,%1,%2,%3},{%4,%5,%6,%7},{%8,%9},{%0,%1,%2,%3};"         \
                 : "+f"(d[0]), "+f"(d[1]), "+f"(d[2]), "+f"(d[3])             \
                 : "r"(a[0]), "r"(a[1]), "r"(a[2]), "r"(a[3]),                \
                   "r"(b0v), "r"(b1v))
#define MMA16816H(d, a, b0v, b1v)                                             \
    asm volatile("mma.sync.aligned.m16n8k16.row.col.f32.f16.f16.f32 "         \
                 "{%0,%1,%2,%3},{%4,%5,%6,%7},{%8,%9},{%0,%1,%2,%3};"         \
                 : "+f"(d[0]), "+f"(d[1]), "+f"(d[2]), "+f"(d[3])             \
                 : "r"(a[0]), "r"(a[1]), "r"(a[2]), "r"(a[3]),                \
                   "r"(b0v), "r"(b1v))
#define CP16(smaddr, gptr)                                                    \
    asm volatile("cp.async.cg.shared.global [%0], [%1], 16;" :: "r"(smaddr), "l"(gptr))
#define CP_COMMIT asm volatile("cp.async.commit_group;")

__device__ __forceinline__ void split2(float x, float y,
                                       unsigned& hi, unsigned& lo) {
    __nv_bfloat16 hx = __float2bfloat16_rn(x);
    __nv_bfloat16 hy = __float2bfloat16_rn(y);
    float rx = x - __bfloat162float(hx);
    float ry = y - __bfloat162float(hy);
    __nv_bfloat16 lx = __float2bfloat16_rn(rx);
    __nv_bfloat16 ly = __float2bfloat16_rn(ry);
    __nv_bfloat162 h2 = __nv_bfloat162(hx, hy);
    __nv_bfloat162 l2 = __nv_bfloat162(lx, ly);
    hi = *(unsigned*)&h2;
    lo = *(unsigned*)&l2;
}

__device__ __forceinline__ unsigned packh2(float x, float y) {
    __half2 h = __floats2half2_rn(x, y);
    return *(unsigned*)&h;
}

// ================= ONE fused conversion / packing / table kernel =============
#define CN0 4194304
#define CN1 1048576
#define CN2 262144
#define CN3 262144
#define CN4 1048576
#define CN5 3072
#define CN6 131072
#define CTOT (CN0 + CN1 + CN2 + CN3 + CN4 + CN5 + CN6)

__global__ void convert_all(const float* __restrict__ x,
                            const float* __restrict__ Wq,
                            const float* __restrict__ Wk,
                            const float* __restrict__ Wv,
                            const float* __restrict__ Wo,
                            const float* __restrict__ bq,
                            const float* __restrict__ bk,
                            const float* __restrict__ bv) {
    long i = (long)blockIdx.x * blockDim.x + threadIdx.x;
    if (i < CN0) {
        float4 v = ((const float4*)x)[i];
        uint2 h, l;
        split2(v.x, v.y, h.x, l.x);
        split2(v.z, v.w, h.y, l.y);
        ((uint2*)g_xh)[i] = h;
        ((uint2*)g_xl)[i] = l;
    } else if (i < CN0 + CN1 + CN2 + CN3) {
        long j;
        int srcN, off;
        const float* src;
        if (i < CN0 + CN1)      { j = i - CN0;               srcN = 2048; off = 0;    src = Wq; }
        else if (i < CN0 + CN1 + CN2) { j = i - CN0 - CN1;   srcN = 512;  off = 2048; src = Wk; }
        else                    { j = i - CN0 - CN1 - CN2;   srcN = 512;  off = 2560; src = Wv; }
        int rw = srcN >> 2;
        int r = (int)(j / rw), c = (int)(j % rw) * 4;
        float4 v = *(const float4*)&src[(size_t)r * srcN + c];
        uint2 h, l;
        split2(v.x, v.y, h.x, l.x);
        split2(v.z, v.w, h.y, l.y);
        size_t d = (size_t)r * NQKV + off + c;
        *(uint2*)&g_wqh[d] = h;
        *(uint2*)&g_wql[d] = l;
    } else if (i < CN0 + CN1 + CN2 + CN3 + CN4) {
        long j = i - (CN0 + CN1 + CN2 + CN3);
        float4 v = ((const float4*)Wo)[j];
        uint2 h;
        h.x = packh2(v.x * 32.0f, v.y * 32.0f);
        h.y = packh2(v.z * 32.0f, v.w * 32.0f);
        ((uint2*)g_woh)[j] = h;
    } else if (i < CN0 + CN1 + CN2 + CN3 + CN4 + CN5) {
        int j = (int)(i - (CN0 + CN1 + CN2 + CN3 + CN4));
        g_bqkv[j] = (j < 2048) ? bq[j] : (j < 2560) ? bk[j - 2048] : bv[j - 2560];
    } else {
        int j = (int)(i - (CN0 + CN1 + CN2 + CN3 + CN4 + CN5));
        int s = j >> 6, f = j & 63;
        float inv_freq = powf(10000.0f, -(float)f / 64.0f);
        float ang = (float)s * inv_freq;
        g_rope[j] = make_float2(cosf(ang), sinf(ang));
    }
}

// ======================== bf16 3-term GEMM mainloop ==========================
#define LDA 40
#define LDB 136
#define ST_EL 18944   // per-stage smem elements: 2*128*40 + 2*32*136

struct GemmAcc { float a[4][4][4]; };

// 3-stage cp.async pipeline; mma issued term-major (RAW distance 8).
__device__ __forceinline__ void gemm_mainloop(
    const __nv_bfloat16* __restrict__ Ahg, const __nv_bfloat16* __restrict__ Alg,
    const __nv_bfloat16* __restrict__ Bhg, const __nv_bfloat16* __restrict__ Blg,
    int K, int N, int row0, int col0, unsigned smBase, GemmAcc& acc) {
    const int tid = threadIdx.x;
    const int lane = tid & 31;
    const int warp = tid >> 5;
    const int wm = (warp >> 2) * 64;
    const int wn = (warp & 3) * 32;
    const int NT = K / 32;

    auto issue = [&](int st, int k0) {
        unsigned sb = smBase + st * (ST_EL * 2);
        #pragma unroll
        for (int j = 0; j < 2; j++) {
            int c = tid + j * 256;
            int r = c >> 2, c8 = (c & 3) * 8;
            unsigned so = (unsigned)(r * LDA + c8) * 2;
            CP16(sb + so, &Ahg[(size_t)(row0 + r) * K + k0 + c8]);
            CP16(sb + 10240 + so, &Alg[(size_t)(row0 + r) * K + k0 + c8]);
        }
        #pragma unroll
        for (int j = 0; j < 2; j++) {
            int c = tid + j * 256;
            int r = c >> 4, c8 = (c & 15) * 8;
            unsigned so = (unsigned)(r * LDB + c8) * 2;
            CP16(sb + 20480 + so, &Bhg[(size_t)(k0 + r) * N + col0 + c8]);
            CP16(sb + 29184 + so, &Blg[(size_t)(k0 + r) * N + col0 + c8]);
        }
    };

    issue(0, 0);
    CP_COMMIT;
    issue(1, 32);
    CP_COMMIT;

    for (int it = 0; it < NT; it++) {
        if (it == NT - 1) {
            asm volatile("cp.async.wait_group 0;");
        } else {
            asm volatile("cp.async.wait_group 1;");
        }
        __syncthreads();
        if (it + 2 < NT) {
            issue((it + 2) % 3, (it + 2) * 32);
            CP_COMMIT;
        }

        unsigned sb = smBase + (it % 3) * (ST_EL * 2);
        const unsigned aBaseH = sb, aBaseL = sb + 10240;
        const unsigned bBaseH = sb + 20480, bBaseL = sb + 29184;

        #pragma unroll
        for (int ks = 0; ks < 2; ks++) {
            unsigned ah[4][4], al[4][4];
            #pragma unroll
            for (int im = 0; im < 4; im++) {
                unsigned off =
                    ((wm + im * 16 + (lane & 15)) * LDA + ks * 16 + (lane >> 4) * 8) * 2;
                LDSM4(ah[im], aBaseH + off);
                LDSM4(al[im], aBaseL + off);
            }
            int krow = ks * 16 + (lane & 7) + ((lane >> 3) & 1) * 8;
            #pragma unroll
            for (int pr = 0; pr < 2; pr++) {
                unsigned bh[4], bl[4];
                unsigned off = (krow * LDB + wn + pr * 16 + (lane >> 4) * 8) * 2;
                LDSM4T(bh, bBaseH + off);
                LDSM4T(bl, bBaseL + off);
                // term-major issue: 8 independent accumulators between reuses
                #pragma unroll
                for (int im = 0; im < 4; im++)
                    MMA16816(acc.a[im][pr * 2 + 0], ah[im], bh[0], bh[1]);
                #pragma unroll
                for (int im = 0; im < 4; im++)
                    MMA16816(acc.a[im][pr * 2 + 1], ah[im], bh[2], bh[3]);
                #pragma unroll
                for (int im = 0; im < 4; im++)
                    MMA16816(acc.a[im][pr * 2 + 0], ah[im], bl[0], bl[1]);
                #pragma unroll
                for (int im = 0; im < 4; im++)
                    MMA16816(acc.a[im][pr * 2 + 1], ah[im], bl[2], bl[3]);
                #pragma unroll
                for (int im = 0; im < 4; im++)
                    MMA16816(acc.a[im][pr * 2 + 0], al[im], bh[0], bh[1]);
                #pragma unroll
                for (int im = 0; im < 4; im++)
                    MMA16816(acc.a[im][pr * 2 + 1], al[im], bh[2], bh[3]);
            }
        }
    }
    __syncthreads();   // mainloop smem dead; safe for epilogue reuse
}

// ============= QKV GEMM with fused bias + RoPE + hi/lo split epilogue ========
#define STF 132   // fp32 smem stride for epilogue tile

__global__ __launch_bounds__(256) void gemm_qkv_fused(
    const __nv_bfloat16* __restrict__ Ahg, const __nv_bfloat16* __restrict__ Alg,
    const __nv_bfloat16* __restrict__ Bhg, const __nv_bfloat16* __restrict__ Blg,
    const float* __restrict__ bias) {
    extern __shared__ __nv_bfloat16 smem[];
    const unsigned smBase = (unsigned)__cvta_generic_to_shared(smem);

    const int tid = threadIdx.x;
    const int lane = tid & 31;
    const int warp = tid >> 5;
    const int wm = (warp >> 2) * 64;
    const int wn = (warp & 3) * 32;
    const int row0 = blockIdx.y * 128;
    const int col0 = blockIdx.x * 128;

    GemmAcc acc = {};
    gemm_mainloop(Ahg, Alg, Bhg, Blg, D, NQKV, row0, col0, smBase, acc);

    // ---- stage fp32 tile (with bias) in smem ----
    float* st = (float*)smem;
    const int qr = lane >> 2, qc = lane & 3;
    #pragma unroll
    for (int im = 0; im < 4; im++) {
        #pragma unroll
        for (int jn = 0; jn < 4; jn++) {
            int rr = wm + im * 16 + qr;
            int cc = wn + jn * 8 + 2 * qc;
            float b0v = bias[col0 + cc], b1v = bias[col0 + cc + 1];
            st[rr * STF + cc]           = acc.a[im][jn][0] + b0v;
            st[rr * STF + cc + 1]       = acc.a[im][jn][1] + b1v;
            st[(rr + 8) * STF + cc]     = acc.a[im][jn][2] + b0v;
            st[(rr + 8) * STF + cc + 1] = acc.a[im][jn][3] + b1v;
        }
    }
    __syncthreads();

    const int tile = col0 >> 7;      // head tile: 0-15 q, 16-19 k, 20-23 v
    const int bb = row0 >> 11;
    const float scale = 0.08838834764831845f;

    if (tile < 20) {   // q or k: rope (table) + split (bf16)
        bool isq = tile < 16;
        int hh = isq ? tile : tile - 16;
        int nh = isq ? H : G;
        __nv_bfloat16* dh = isq ? g_qsh : g_ksh;
        __nv_bfloat16* dl = isq ? g_qsl : g_ksl;
        float sc = isq ? scale : 1.0f;
        #pragma unroll 4
        for (int t = 0; t < 16; t++) {
            int idx = tid + t * 256;
            int r = idx >> 5;
            int i2 = (idx & 31) * 2;
            int s = (row0 + r) & (S - 1);
            float a0 = st[r * STF + i2],      a1 = st[r * STF + i2 + 1];
            float c0 = st[r * STF + i2 + 64], c1 = st[r * STF + i2 + 65];
            float4 tcs = *(const float4*)&g_rope[(size_t)s * 64 + i2];
            float o10 = (a0 * tcs.x - c0 * tcs.y) * sc;
            float o11 = (a1 * tcs.z - c1 * tcs.w) * sc;
            float o20 = (c0 * tcs.x + a0 * tcs.y) * sc;
            float o21 = (c1 * tcs.z + a1 * tcs.w) * sc;
            unsigned h1, l1, h2, l2;
            split2(o10, o11, h1, l1);
            split2(o20, o21, h2, l2);
            size_t dst = ((size_t)(bb * nh + hh) * S + s) * HD + i2;
            *(unsigned*)&dh[dst] = h1;
            *(unsigned*)&dl[dst] = l1;
            *(unsigned*)&dh[dst + 64] = h2;
            *(unsigned*)&dl[dst + 64] = l2;
        }
    } else {           // v: single fp16
        int gg = tile - 20;
        #pragma unroll 4
        for (int t = 0; t < 32; t++) {
            int idx = tid + t * 256;
            int r = idx >> 6;
            int i2 = (idx & 63) * 2;
            int s = (row0 + r) & (S - 1);
            float v0 = st[r * STF + i2], v1 = st[r * STF + i2 + 1];
            size_t dst = ((size_t)(bb * G + gg) * S + s) * HD + i2;
            *(unsigned*)&g_vsh[dst] = packh2(v0, v1);
        }
    }
}

// ============ output projection: A fp16 single x W fp16 single ===============
#define STH_EL 9472   // per-stage elements: 128*40 + 32*136

__global__ __launch_bounds__(256) void gemm_out_h(
    const __half* __restrict__ Ag, const __half* __restrict__ Bg,
    const float* __restrict__ bias, float* __restrict__ C,
    int M, int N, int K) {
    extern __shared__ __nv_bfloat16 smemb[];
    __half* smem = (__half*)smemb;
    const unsigned smBase = (unsigned)__cvta_generic_to_shared(smem);

    const int tid = threadIdx.x;
    const int lane = tid & 31;
    const int warp = tid >> 5;
    const int wm = (warp >> 2) * 64;
    const int wn = (warp & 3) * 32;
    const int row0 = blockIdx.y * 128;
    const int col0 = blockIdx.x * 128;
    const int NT = K / 32;

    float acc[4][4][4] = {};

    auto issue = [&](int st, int k0) {
        unsigned sb = smBase + st * (STH_EL * 2);
        #pragma unroll
        for (int j = 0; j < 2; j++) {
            int c = tid + j * 256;
            int r = c >> 2, c8 = (c & 3) * 8;
            unsigned so = (unsigned)(r * LDA + c8) * 2;
            CP16(sb + so, &Ag[(size_t)(row0 + r) * K + k0 + c8]);
        }
        #pragma unroll
        for (int j = 0; j < 2; j++) {
            int c = tid + j * 256;
            int r = c >> 4, c8 = (c & 15) * 8;
            unsigned so = (unsigned)(r * LDB + c8) * 2;
            CP16(sb + 10240 + so, &Bg[(size_t)(k0 + r) * N + col0 + c8]);
        }
    };

    issue(0, 0);
    CP_COMMIT;
    issue(1, 32);
    CP_COMMIT;

    for (int it = 0; it < NT; it++) {
        if (it == NT - 1) {
            asm volatile("cp.async.wait_group 0;");
        } else {
            asm volatile("cp.async.wait_group 1;");
        }
        __syncthreads();
        if (it + 2 < NT) {
            issue((it + 2) % 3, (it + 2) * 32);
            CP_COMMIT;
        }

        unsigned sb = smBase + (it % 3) * (STH_EL * 2);
        const unsigned aBase = sb;
        const unsigned bBase = sb + 10240;

        #pragma unroll
        for (int ks = 0; ks < 2; ks++) {
            unsigned ah[4][4];
            #pragma unroll
            for (int im = 0; im < 4; im++) {
                unsigned off =
                    ((wm + im * 16 + (lane & 15)) * LDA + ks * 16 + (lane >> 4) * 8) * 2;
                LDSM4(ah[im], aBase + off);
            }
            int krow = ks * 16 + (lane & 7) + ((lane >> 3) & 1) * 8;
            #pragma unroll
            for (int pr = 0; pr < 2; pr++) {
                unsigned bh[4];
                unsigned off = (krow * LDB + wn + pr * 16 + (lane >> 4) * 8) * 2;
                LDSM4T(bh, bBase + off);
                #pragma unroll
                for (int im = 0; im < 4; im++) {
                    MMA16816H(acc[im][pr * 2 + 0], ah[im], bh[0], bh[1]);
                    MMA16816H(acc[im][pr * 2 + 1], ah[im], bh[2], bh[3]);
                }
            }
        }
    }

    const float inv32 = 1.0f / 32.0f;
    const int qr = lane >> 2, qc = lane & 3;
    #pragma unroll
    for (int im = 0; im < 4; im++) {
        #pragma unroll
        for (int jn = 0; jn < 4; jn++) {
            int row = row0 + wm + im * 16 + qr;
            int col = col0 + wn + jn * 8 + 2 * qc;
            float b0v = bias[col], b1v = bias[col + 1];
            float2 o0 = make_float2(acc[im][jn][0] * inv32 + b0v,
                                    acc[im][jn][1] * inv32 + b1v);
            float2 o1 = make_float2(acc[im][jn][2] * inv32 + b0v,
                                    acc[im][jn][3] * inv32 + b1v);
            *(float2*)&C[(size_t)row * N + col] = o0;
            *(float2*)&C[(size_t)(row + 8) * N + col] = o1;
        }
    }
}

// ====== Flash attention: 128-row q tiles, QK bf16 3-term, PV fp16 1-term =====
#define LQ 136

__global__ __launch_bounds__(256) void flash_tc() {
    extern __shared__ __nv_bfloat16 smb[];
    __nv_bfloat16* Qh = smb;
    __nv_bfloat16* Ql = Qh + 128 * LQ;
    __nv_bfloat16* Kh = Ql + 128 * LQ;
    __nv_bfloat16* Kl = Kh + 64 * LQ;
    __half*        Vh = (__half*)(Kl + 64 * LQ);

    const int tid  = threadIdx.x;
    const int lane = tid & 31;
    const int warp = tid >> 5;
    const int qtile = gridDim.z - 1 - blockIdx.z;
    const int h  = blockIdx.x;
    const int b  = blockIdx.y;
    const int g  = h / (H / G);
    const int q0 = qtile * 128;
    const int wm = warp * 16;

    const unsigned qBH = (unsigned)__cvta_generic_to_shared(Qh);
    const unsigned qBL = (unsigned)__cvta_generic_to_shared(Ql);
    const unsigned kBH = (unsigned)__cvta_generic_to_shared(Kh);
    const unsigned kBL = (unsigned)__cvta_generic_to_shared(Kl);
    const unsigned vBH = (unsigned)__cvta_generic_to_shared(Vh);

    #pragma unroll
    for (int it = 0; it < 8; it++) {
        int i4 = tid + it * 256;
        int r  = i4 >> 4;
        int c8 = (i4 & 15) * 8;
        size_t gi = ((size_t)(b * H + h) * S + q0 + r) * HD + c8;
        *(uint4*)&Qh[r * LQ + c8] = *(const uint4*)&g_qsh[gi];
        *(uint4*)&Ql[r * LQ + c8] = *(const uint4*)&g_qsl[gi];
    }

    const int gid = lane >> 2, tig = lane & 3;
    const int row0g = q0 + wm + gid;
    const int row1g = row0g + 8;
    const int wmaxrow = q0 + wm + 15;

    float rm0 = -1e30f, rm1 = -1e30f, rl0 = 0.0f, rl1 = 0.0f;
    float oacc[16][4] = {};

    const int NKT = 2 * qtile + 2;
    for (int kt = 0; kt < NKT; kt++) {
        const int k0 = kt * 64;
        __syncthreads();
        #pragma unroll
        for (int it = 0; it < 4; it++) {
            int i4 = tid + it * 256;
            int r  = i4 >> 4;
            int c8 = (i4 & 15) * 8;
            size_t gi = ((size_t)(b * G + g) * S + k0 + r) * HD + c8;
            unsigned so = r * LQ + c8;
            *(uint4*)&Kh[so] = *(const uint4*)&g_ksh[gi];
            *(uint4*)&Kl[so] = *(const uint4*)&g_ksl[gi];
            *(uint4*)&Vh[so] = *(const uint4*)&g_vsh[gi];
        }
        __syncthreads();

        if (k0 > wmaxrow) continue;

        // ---- S = Q @ K^T (bf16 3-term, nb-paired, RAW distance 4) ----
        float sacc[8][4] = {};
        #pragma unroll
        for (int ks = 0; ks < 8; ks++) {
            unsigned ah[4], al[4];
            unsigned offa = ((wm + (lane & 15)) * LQ + ks * 16 + (lane >> 4) * 8) * 2;
            LDSM4(ah, qBH + offa);
            LDSM4(al, qBL + offa);
            #pragma unroll
            for (int np = 0; np < 2; np++) {
                unsigned kh0[4], kl0[4], kh1[4], kl1[4];
                unsigned ob0 = (((2 * np + 0) * 16 + (lane >> 4) * 8 + (lane & 7)) * LQ +
                                ks * 16 + ((lane >> 3) & 1) * 8) * 2;
                unsigned ob1 = (((2 * np + 1) * 16 + (lane >> 4) * 8 + (lane & 7)) * LQ +
                                ks * 16 + ((lane >> 3) & 1) * 8) * 2;
                LDSM4(kh0, kBH + ob0);
                LDSM4(kl0, kBL + ob0);
                LDSM4(kh1, kBH + ob1);
                LDSM4(kl1, kBL + ob1);
                MMA16816(sacc[4 * np + 0], ah, kh0[0], kh0[1]);
                MMA16816(sacc[4 * np + 1], ah, kh0[2], kh0[3]);
                MMA16816(sacc[4 * np + 2], ah, kh1[0], kh1[1]);
                MMA16816(sacc[4 * np + 3], ah, kh1[2], kh1[3]);
                MMA16816(sacc[4 * np + 0], ah, kl0[0], kl0[1]);
                MMA16816(sacc[4 * np + 1], ah, kl0[2], kl0[3]);
                MMA16816(sacc[4 * np + 2], ah, kl1[0], kl1[1]);
                MMA16816(sacc[4 * np + 3], ah, kl1[2], kl1[3]);
                MMA16816(sacc[4 * np + 0], al, kh0[0], kh0[1]);
                MMA16816(sacc[4 * np + 1], al, kh0[2], kh0[3]);
                MMA16816(sacc[4 * np + 2], al, kh1[0], kh1[1]);
                MMA16816(sacc[4 * np + 3], al, kh1[2], kh1[3]);
            }
        }

        if (k0 + 63 > row0g) {
            #pragma unroll
            for (int nt = 0; nt < 8; nt++) {
                int colg = k0 + nt * 8 + 2 * tig;
                if (colg > row0g)     sacc[nt][0] = -1e30f;
                if (colg + 1 > row0g) sacc[nt][1] = -1e30f;
                if (colg > row1g)     sacc[nt][2] = -1e30f;
                if (colg + 1 > row1g) sacc[nt][3] = -1e30f;
            }
        }

        // ---- online softmax ----
        float mx0 = rm0, mx1 = rm1;
        #pragma unroll
        for (int nt = 0; nt < 8; nt++) {
            mx0 = fmaxf(mx0, fmaxf(sacc[nt][0], sacc[nt][1]));
            mx1 = fmaxf(mx1, fmaxf(sacc[nt][2], sacc[nt][3]));
        }
        mx0 = fmaxf(mx0, __shfl_xor_sync(0xffffffff, mx0, 1));
        mx0 = fmaxf(mx0, __shfl_xor_sync(0xffffffff, mx0, 2));
        mx1 = fmaxf(mx1, __shfl_xor_sync(0xffffffff, mx1, 1));
        mx1 = fmaxf(mx1, __shfl_xor_sync(0xffffffff, mx1, 2));
        float sc0 = __expf(rm0 - mx0);
        float sc1 = __expf(rm1 - mx1);
        rm0 = mx0; rm1 = mx1;
        float sum0 = 0.0f, sum1 = 0.0f;
        #pragma unroll
        for (int nt = 0; nt < 8; nt++) {
            sacc[nt][0] = __expf(sacc[nt][0] - mx0);
            sacc[nt][1] = __expf(sacc[nt][1] - mx0);
            sacc[nt][2] = __expf(sacc[nt][2] - mx1);
            sacc[nt][3] = __expf(sacc[nt][3] - mx1);
            sum0 += sacc[nt][0] + sacc[nt][1];
            sum1 += sacc[nt][2] + sacc[nt][3];
        }
        sum0 += __shfl_xor_sync(0xffffffff, sum0, 1);
        sum0 += __shfl_xor_sync(0xffffffff, sum0, 2);
        sum1 += __shfl_xor_sync(0xffffffff, sum1, 1);
        sum1 += __shfl_xor_sync(0xffffffff, sum1, 2);
        rl0 = rl0 * sc0 + sum0;
        rl1 = rl1 * sc1 + sum1;
        #pragma unroll
        for (int nt = 0; nt < 16; nt++) {
            oacc[nt][0] *= sc0; oacc[nt][1] *= sc0;
            oacc[nt][2] *= sc1; oacc[nt][3] *= sc1;
        }

        // ---- O += P @ V (fp16 single-term) ----
        #pragma unroll
        for (int j = 0; j < 4; j++) {
            unsigned ph[4];
            ph[0] = packh2(sacc[2 * j][0],     sacc[2 * j][1]);
            ph[1] = packh2(sacc[2 * j][2],     sacc[2 * j][3]);
            ph[2] = packh2(sacc[2 * j + 1][0], sacc[2 * j + 1][1]);
            ph[3] = packh2(sacc[2 * j + 1][2], sacc[2 * j + 1][3]);
            #pragma unroll
            for (int nb = 0; nb < 8; nb++) {
                unsigned vh4[4];
                unsigned offv = ((j * 16 + (lane & 7) + ((lane >> 3) & 1) * 8) * LQ +
                                 nb * 16 + (lane >> 4) * 8) * 2;
                LDSM4T(vh4, vBH + offv);
                MMA16816H(oacc[2 * nb + 0], ph, vh4[0], vh4[1]);
                MMA16816H(oacc[2 * nb + 1], ph, vh4[2], vh4[3]);
            }
        }
    }

    // ---- finalize: divide by l, store fp16 single ----
    float li0 = 1.0f / rl0, li1 = 1.0f / rl1;
    size_t or0 = (size_t)(b * S + row0g) * (H * HD) + h * HD;
    size_t or1 = (size_t)(b * S + row1g) * (H * HD) + h * HD;
    #pragma unroll
    for (int nt = 0; nt < 16; nt++) {
        int col = nt * 8 + 2 * tig;
        *(unsigned*)&g_ah[or0 + col] = packh2(oacc[nt][0] * li0, oacc[nt][1] * li0);
        *(unsigned*)&g_ah[or1 + col] = packh2(oacc[nt][2] * li1, oacc[nt][3] * li1);
    }
}

// =============================== launch ======================================
extern "C" void kernel_launch(void* const* d_in, const int* in_sizes, int n_in,
                              void* d_out, int out_size) {
    const float* x  = (const float*)d_in[0];
    const float* Wq = (const float*)d_in[1];
    const float* bq = (const float*)d_in[2];
    const float* Wk = (const float*)d_in[3];
    const float* bk = (const float*)d_in[4];
    const float* Wv = (const float*)d_in[5];
    const float* bv = (const float*)d_in[6];
    const float* Wo = (const float*)d_in[7];
    const float* bo = (const float*)d_in[8];
    float* out = (float*)d_out;

    __nv_bfloat16 *xh, *xl, *wqh, *wql;
    __half *woh, *ah;
    float *bqkv;
    cudaGetSymbolAddress((void**)&xh, g_xh);
    cudaGetSymbolAddress((void**)&xl, g_xl);
    cudaGetSymbolAddress((void**)&wqh, g_wqh);
    cudaGetSymbolAddress((void**)&wql, g_wql);
    cudaGetSymbolAddress((void**)&woh, g_woh);
    cudaGetSymbolAddress((void**)&ah, g_ah);
    cudaGetSymbolAddress((void**)&bqkv, g_bqkv);

    const int M = B * S;  // 8192

    convert_all<<<(CTOT + 255) / 256, 256>>>(x, Wq, Wk, Wv, Wo, bq, bk, bv);

    size_t gsm = (size_t)3 * ST_EL * sizeof(__nv_bfloat16);  // 113664 B
    cudaFuncSetAttribute(gemm_qkv_fused, cudaFuncAttributeMaxDynamicSharedMemorySize, (int)gsm);
    size_t gsmh = (size_t)3 * STH_EL * sizeof(__half);       // 56832 B
    cudaFuncSetAttribute(gemm_out_h, cudaFuncAttributeMaxDynamicSharedMemorySize, (int)gsmh);

    // ---- fused QKV projection + bias + RoPE + split ----
    gemm_qkv_fused<<<dim3(NQKV / 128, M / 128), 256, gsm>>>(xh, xl, wqh, wql, bqkv);

    // ---- flash attention (128-row q tiles, heavy-first via z) ----
    size_t smem = (size_t)(2 * 128 + 3 * 64) * LQ * sizeof(__nv_bfloat16);  // 121856 B
    cudaFuncSetAttribute(flash_tc, cudaFuncAttributeMaxDynamicSharedMemorySize, (int)smem);
    flash_tc<<<dim3(H, B, S / 128), 256, smem>>>();

    // ---- output projection (fp16 single-term) ----
    gemm_out_h<<<dim3(D / 128, M / 128), 256, gsmh>>>(
        ah, woh, bo, out, M, D, H * HD);
}

// round 14
// speedup vs baseline: 1.1288x; 1.0035x over previous
#include <cuda_runtime.h>
#include <cuda_bf16.h>
#include <cuda_fp16.h>
#include <math.h>

#define B 4
#define S 2048
#define D 2048
#define H 16
#define G 4
#define HD 128
#define NQKV 3072   // packed q(2048) | k(512) | v(512)

// ------------------------- scratch (device globals, no allocs) --------------
__device__ __nv_bfloat16 g_xh[(size_t)B * S * D];
__device__ __nv_bfloat16 g_xl[(size_t)B * S * D];
__device__ __nv_bfloat16 g_wqh[(size_t)D * NQKV];          // packed Wqkv hi [k][n]
__device__ __nv_bfloat16 g_wql[(size_t)D * NQKV];
__device__ __half        g_woh[(size_t)H * HD * D];        // Wo*32 (fp16 single)
__device__ __half        g_ah[(size_t)B * S * H * HD];     // attn out (fp16 single)
__device__ float         g_bqkv[NQKV];
__device__ float2        g_rope[(size_t)S * 64];           // (cos,sin) per (s, freq)
// pre-split, roped operands for flash
__device__ __nv_bfloat16 g_qsh[(size_t)B * H * S * HD];
__device__ __nv_bfloat16 g_qsl[(size_t)B * H * S * HD];
__device__ __nv_bfloat16 g_ksh[(size_t)B * G * S * HD];
__device__ __nv_bfloat16 g_ksl[(size_t)B * G * S * HD];
__device__ __half        g_vsh[(size_t)B * G * S * HD];

// ============================ shared PTX helpers =============================
#define LDSM4(R, addr)                                                        \
    asm volatile("ldmatrix.sync.aligned.m8n8.x4.shared.b16 {%0,%1,%2,%3}, [%4];" \
                 : "=r"(R[0]), "=r"(R[1]), "=r"(R[2]), "=r"(R[3]) : "r"(addr))
#define LDSM4T(R, addr)                                                       \
    asm volatile("ldmatrix.sync.aligned.m8n8.x4.trans.shared.b16 {%0,%1,%2,%3}, [%4];" \
                 : "=r"(R[0]), "=r"(R[1]), "=r"(R[2]), "=r"(R[3]) : "r"(addr))
#define MMA16816(d, a, b0v, b1v)                                              \
    asm volatile("mma.sync.aligned.m16n8k16.row.col.f32.bf16.bf16.f32 "       \
                 "{%0,%1,%2,%3},{%4,%5,%6,%7},{%8,%9},{%0,%1,%2,%3};"         \
                 : "+f"(d[0]), "+f"(d[1]), "+f"(d[2]), "+f"(d[3])             \
                 : "r"(a[0]), "r"(a[1]), "r"(a[2]), "r"(a[3]),                \
                   "r"(b0v), "r"(b1v))
#define MMA16816H(d, a, b0v, b1v)                                             \
    asm volatile("mma.sync.aligned.m16n8k16.row.col.f32.f16.f16.f32 "         \
                 "{%0,%1,%2,%3},{%4,%5,%6,%7},{%8,%9},{%0,%1,%2,%3};"         \
                 : "+f"(d[0]), "+f"(d[1]), "+f"(d[2]), "+f"(d[3])             \
                 : "r"(a[0]), "r"(a[1]), "r"(a[2]), "r"(a[3]),                \
                   "r"(b0v), "r"(b1v))
#define CP16(smaddr, gptr)                                                    \
    asm volatile("cp.async.cg.shared.global [%0], [%1], 16;" :: "r"(smaddr), "l"(gptr))
#define CP_COMMIT asm volatile("cp.async.commit_group;")

__device__ __forceinline__ void split2(float x, float y,
                                       unsigned& hi, unsigned& lo) {
    __nv_bfloat16 hx = __float2bfloat16_rn(x);
    __nv_bfloat16 hy = __float2bfloat16_rn(y);
    float rx = x - __bfloat162float(hx);
    float ry = y - __bfloat162float(hy);
    __nv_bfloat16 lx = __float2bfloat16_rn(rx);
    __nv_bfloat16 ly = __float2bfloat16_rn(ry);
    __nv_bfloat162 h2 = __nv_bfloat162(hx, hy);
    __nv_bfloat162 l2 = __nv_bfloat162(lx, ly);
    hi = *(unsigned*)&h2;
    lo = *(unsigned*)&l2;
}

__device__ __forceinline__ unsigned packh2(float x, float y) {
    __half2 h = __floats2half2_rn(x, y);
    return *(unsigned*)&h;
}

// ================= ONE fused conversion / packing / table kernel =============
#define CN0 4194304
#define CN1 1048576
#define CN2 262144
#define CN3 262144
#define CN4 1048576
#define CN5 3072
#define CN6 131072
#define CTOT (CN0 + CN1 + CN2 + CN3 + CN4 + CN5 + CN6)

__global__ void convert_all(const float* __restrict__ x,
                            const float* __restrict__ Wq,
                            const float* __restrict__ Wk,
                            const float* __restrict__ Wv,
                            const float* __restrict__ Wo,
                            const float* __restrict__ bq,
                            const float* __restrict__ bk,
                            const float* __restrict__ bv) {
    long i = (long)blockIdx.x * blockDim.x + threadIdx.x;
    if (i < CN0) {
        float4 v = ((const float4*)x)[i];
        uint2 h, l;
        split2(v.x, v.y, h.x, l.x);
        split2(v.z, v.w, h.y, l.y);
        ((uint2*)g_xh)[i] = h;
        ((uint2*)g_xl)[i] = l;
    } else if (i < CN0 + CN1 + CN2 + CN3) {
        long j;
        int srcN, off;
        const float* src;
        if (i < CN0 + CN1)      { j = i - CN0;               srcN = 2048; off = 0;    src = Wq; }
        else if (i < CN0 + CN1 + CN2) { j = i - CN0 - CN1;   srcN = 512;  off = 2048; src = Wk; }
        else                    { j = i - CN0 - CN1 - CN2;   srcN = 512;  off = 2560; src = Wv; }
        int rw = srcN >> 2;
        int r = (int)(j / rw), c = (int)(j % rw) * 4;
        float4 v = *(const float4*)&src[(size_t)r * srcN + c];
        uint2 h, l;
        split2(v.x, v.y, h.x, l.x);
        split2(v.z, v.w, h.y, l.y);
        size_t d = (size_t)r * NQKV + off + c;
        *(uint2*)&g_wqh[d] = h;
        *(uint2*)&g_wql[d] = l;
    } else if (i < CN0 + CN1 + CN2 + CN3 + CN4) {
        long j = i - (CN0 + CN1 + CN2 + CN3);
        float4 v = ((const float4*)Wo)[j];
        uint2 h;
        h.x = packh2(v.x * 32.0f, v.y * 32.0f);
        h.y = packh2(v.z * 32.0f, v.w * 32.0f);
        ((uint2*)g_woh)[j] = h;
    } else if (i < CN0 + CN1 + CN2 + CN3 + CN4 + CN5) {
        int j = (int)(i - (CN0 + CN1 + CN2 + CN3 + CN4));
        g_bqkv[j] = (j < 2048) ? bq[j] : (j < 2560) ? bk[j - 2048] : bv[j - 2560];
    } else {
        int j = (int)(i - (CN0 + CN1 + CN2 + CN3 + CN4 + CN5));
        int s = j >> 6, f = j & 63;
        float inv_freq = powf(10000.0f, -(float)f / 64.0f);
        float ang = (float)s * inv_freq;
        g_rope[j] = make_float2(cosf(ang), sinf(ang));
    }
}

// ======================== bf16 3-term GEMM mainloop ==========================
#define LDA 40
#define LDB 136
#define ST_EL 18944   // per-stage smem elements: 2*128*40 + 2*32*136

struct GemmAcc { float a[4][4][4]; };

// 2-stage cp.async pipeline (smaller smem -> 2 CTAs/SM), term-major mma.
__device__ __forceinline__ void gemm_mainloop2(
    const __nv_bfloat16* __restrict__ Ahg, const __nv_bfloat16* __restrict__ Alg,
    const __nv_bfloat16* __restrict__ Bhg, const __nv_bfloat16* __restrict__ Blg,
    int K, int N, int row0, int col0, unsigned smBase, GemmAcc& acc) {
    const int tid = threadIdx.x;
    const int lane = tid & 31;
    const int warp = tid >> 5;
    const int wm = (warp >> 2) * 64;
    const int wn = (warp & 3) * 32;
    const int NT = K / 32;

    auto issue = [&](int st, int k0) {
        unsigned sb = smBase + st * (ST_EL * 2);
        #pragma unroll
        for (int j = 0; j < 2; j++) {
            int c = tid + j * 256;
            int r = c >> 2, c8 = (c & 3) * 8;
            unsigned so = (unsigned)(r * LDA + c8) * 2;
            CP16(sb + so, &Ahg[(size_t)(row0 + r) * K + k0 + c8]);
            CP16(sb + 10240 + so, &Alg[(size_t)(row0 + r) * K + k0 + c8]);
        }
        #pragma unroll
        for (int j = 0; j < 2; j++) {
            int c = tid + j * 256;
            int r = c >> 4, c8 = (c & 15) * 8;
            unsigned so = (unsigned)(r * LDB + c8) * 2;
            CP16(sb + 20480 + so, &Bhg[(size_t)(k0 + r) * N + col0 + c8]);
            CP16(sb + 29184 + so, &Blg[(size_t)(k0 + r) * N + col0 + c8]);
        }
    };

    issue(0, 0);
    CP_COMMIT;

    for (int it = 0; it < NT; it++) {
        if (it + 1 < NT) {
            issue((it + 1) & 1, (it + 1) * 32);
            CP_COMMIT;
            asm volatile("cp.async.wait_group 1;");
        } else {
            asm volatile("cp.async.wait_group 0;");
        }
        __syncthreads();

        unsigned sb = smBase + (it & 1) * (ST_EL * 2);
        const unsigned aBaseH = sb, aBaseL = sb + 10240;
        const unsigned bBaseH = sb + 20480, bBaseL = sb + 29184;

        #pragma unroll
        for (int ks = 0; ks < 2; ks++) {
            unsigned ah[4][4], al[4][4];
            #pragma unroll
            for (int im = 0; im < 4; im++) {
                unsigned off =
                    ((wm + im * 16 + (lane & 15)) * LDA + ks * 16 + (lane >> 4) * 8) * 2;
                LDSM4(ah[im], aBaseH + off);
                LDSM4(al[im], aBaseL + off);
            }
            int krow = ks * 16 + (lane & 7) + ((lane >> 3) & 1) * 8;
            #pragma unroll
            for (int pr = 0; pr < 2; pr++) {
                unsigned bh[4], bl[4];
                unsigned off = (krow * LDB + wn + pr * 16 + (lane >> 4) * 8) * 2;
                LDSM4T(bh, bBaseH + off);
                LDSM4T(bl, bBaseL + off);
                #pragma unroll
                for (int im = 0; im < 4; im++)
                    MMA16816(acc.a[im][pr * 2 + 0], ah[im], bh[0], bh[1]);
                #pragma unroll
                for (int im = 0; im < 4; im++)
                    MMA16816(acc.a[im][pr * 2 + 1], ah[im], bh[2], bh[3]);
                #pragma unroll
                for (int im = 0; im < 4; im++)
                    MMA16816(acc.a[im][pr * 2 + 0], ah[im], bl[0], bl[1]);
                #pragma unroll
                for (int im = 0; im < 4; im++)
                    MMA16816(acc.a[im][pr * 2 + 1], ah[im], bl[2], bl[3]);
                #pragma unroll
                for (int im = 0; im < 4; im++)
                    MMA16816(acc.a[im][pr * 2 + 0], al[im], bh[0], bh[1]);
                #pragma unroll
                for (int im = 0; im < 4; im++)
                    MMA16816(acc.a[im][pr * 2 + 1], al[im], bh[2], bh[3]);
            }
        }
        __syncthreads();
    }
}

// ============= QKV GEMM with fused bias + RoPE + hi/lo split epilogue ========
#define STF 132   // fp32 smem stride for epilogue tile

__global__ __launch_bounds__(256, 2) void gemm_qkv_fused(
    const __nv_bfloat16* __restrict__ Ahg, const __nv_bfloat16* __restrict__ Alg,
    const __nv_bfloat16* __restrict__ Bhg, const __nv_bfloat16* __restrict__ Blg,
    const float* __restrict__ bias) {
    extern __shared__ __nv_bfloat16 smem[];
    const unsigned smBase = (unsigned)__cvta_generic_to_shared(smem);

    const int tid = threadIdx.x;
    const int lane = tid & 31;
    const int warp = tid >> 5;
    const int wm = (warp >> 2) * 64;
    const int wn = (warp & 3) * 32;
    const int row0 = blockIdx.y * 128;
    const int col0 = blockIdx.x * 128;

    GemmAcc acc = {};
    gemm_mainloop2(Ahg, Alg, Bhg, Blg, D, NQKV, row0, col0, smBase, acc);

    // ---- stage fp32 tile (with bias) in smem ----
    float* st = (float*)smem;
    const int qr = lane >> 2, qc = lane & 3;
    #pragma unroll
    for (int im = 0; im < 4; im++) {
        #pragma unroll
        for (int jn = 0; jn < 4; jn++) {
            int rr = wm + im * 16 + qr;
            int cc = wn + jn * 8 + 2 * qc;
            float b0v = bias[col0 + cc], b1v = bias[col0 + cc + 1];
            st[rr * STF + cc]           = acc.a[im][jn][0] + b0v;
            st[rr * STF + cc + 1]       = acc.a[im][jn][1] + b1v;
            st[(rr + 8) * STF + cc]     = acc.a[im][jn][2] + b0v;
            st[(rr + 8) * STF + cc + 1] = acc.a[im][jn][3] + b1v;
        }
    }
    __syncthreads();

    const int tile = col0 >> 7;      // head tile: 0-15 q, 16-19 k, 20-23 v
    const int bb = row0 >> 11;
    const float scale = 0.08838834764831845f;

    if (tile < 20) {   // q or k: rope (table) + split (bf16)
        bool isq = tile < 16;
        int hh = isq ? tile : tile - 16;
        int nh = isq ? H : G;
        __nv_bfloat16* dh = isq ? g_qsh : g_ksh;
        __nv_bfloat16* dl = isq ? g_qsl : g_ksl;
        float sc = isq ? scale : 1.0f;
        #pragma unroll 4
        for (int t = 0; t < 16; t++) {
            int idx = tid + t * 256;
            int r = idx >> 5;
            int i2 = (idx & 31) * 2;
            int s = (row0 + r) & (S - 1);
            float a0 = st[r * STF + i2],      a1 = st[r * STF + i2 + 1];
            float c0 = st[r * STF + i2 + 64], c1 = st[r * STF + i2 + 65];
            float4 tcs = *(const float4*)&g_rope[(size_t)s * 64 + i2];
            float o10 = (a0 * tcs.x - c0 * tcs.y) * sc;
            float o11 = (a1 * tcs.z - c1 * tcs.w) * sc;
            float o20 = (c0 * tcs.x + a0 * tcs.y) * sc;
            float o21 = (c1 * tcs.z + a1 * tcs.w) * sc;
            unsigned h1, l1, h2, l2;
            split2(o10, o11, h1, l1);
            split2(o20, o21, h2, l2);
            size_t dst = ((size_t)(bb * nh + hh) * S + s) * HD + i2;
            *(unsigned*)&dh[dst] = h1;
            *(unsigned*)&dl[dst] = l1;
            *(unsigned*)&dh[dst + 64] = h2;
            *(unsigned*)&dl[dst + 64] = l2;
        }
    } else {           // v: single fp16
        int gg = tile - 20;
        #pragma unroll 4
        for (int t = 0; t < 32; t++) {
            int idx = tid + t * 256;
            int r = idx >> 6;
            int i2 = (idx & 63) * 2;
            int s = (row0 + r) & (S - 1);
            float v0 = st[r * STF + i2], v1 = st[r * STF + i2 + 1];
            size_t dst = ((size_t)(bb * G + gg) * S + s) * HD + i2;
            *(unsigned*)&g_vsh[dst] = packh2(v0, v1);
        }
    }
}

// ============ output projection: A fp16 single x W fp16 single ===============
#define STH_EL 9472   // per-stage elements: 128*40 + 32*136

__global__ __launch_bounds__(256) void gemm_out_h(
    const __half* __restrict__ Ag, const __half* __restrict__ Bg,
    const float* __restrict__ bias, float* __restrict__ C,
    int M, int N, int K) {
    extern __shared__ __nv_bfloat16 smemb[];
    __half* smem = (__half*)smemb;
    const unsigned smBase = (unsigned)__cvta_generic_to_shared(smem);

    const int tid = threadIdx.x;
    const int lane = tid & 31;
    const int warp = tid >> 5;
    const int wm = (warp >> 2) * 64;
    const int wn = (warp & 3) * 32;
    const int row0 = blockIdx.y * 128;
    const int col0 = blockIdx.x * 128;
    const int NT = K / 32;

    float acc[4][4][4] = {};

    auto issue = [&](int st, int k0) {
        unsigned sb = smBase + st * (STH_EL * 2);
        #pragma unroll
        for (int j = 0; j < 2; j++) {
            int c = tid + j * 256;
            int r = c >> 2, c8 = (c & 3) * 8;
            unsigned so = (unsigned)(r * LDA + c8) * 2;
            CP16(sb + so, &Ag[(size_t)(row0 + r) * K + k0 + c8]);
        }
        #pragma unroll
        for (int j = 0; j < 2; j++) {
            int c = tid + j * 256;
            int r = c >> 4, c8 = (c & 15) * 8;
            unsigned so = (unsigned)(r * LDB + c8) * 2;
            CP16(sb + 10240 + so, &Bg[(size_t)(k0 + r) * N + col0 + c8]);
        }
    };

    issue(0, 0);
    CP_COMMIT;
    issue(1, 32);
    CP_COMMIT;

    for (int it = 0; it < NT; it++) {
        if (it == NT - 1) {
            asm volatile("cp.async.wait_group 0;");
        } else {
            asm volatile("cp.async.wait_group 1;");
        }
        __syncthreads();
        if (it + 2 < NT) {
            issue((it + 2) % 3, (it + 2) * 32);
            CP_COMMIT;
        }

        unsigned sb = smBase + (it % 3) * (STH_EL * 2);
        const unsigned aBase = sb;
        const unsigned bBase = sb + 10240;

        #pragma unroll
        for (int ks = 0; ks < 2; ks++) {
            unsigned ah[4][4];
            #pragma unroll
            for (int im = 0; im < 4; im++) {
                unsigned off =
                    ((wm + im * 16 + (lane & 15)) * LDA + ks * 16 + (lane >> 4) * 8) * 2;
                LDSM4(ah[im], aBase + off);
            }
            int krow = ks * 16 + (lane & 7) + ((lane >> 3) & 1) * 8;
            #pragma unroll
            for (int pr = 0; pr < 2; pr++) {
                unsigned bh[4];
                unsigned off = (krow * LDB + wn + pr * 16 + (lane >> 4) * 8) * 2;
                LDSM4T(bh, bBase + off);
                #pragma unroll
                for (int im = 0; im < 4; im++) {
                    MMA16816H(acc[im][pr * 2 + 0], ah[im], bh[0], bh[1]);
                    MMA16816H(acc[im][pr * 2 + 1], ah[im], bh[2], bh[3]);
                }
            }
        }
    }

    const float inv32 = 1.0f / 32.0f;
    const int qr = lane >> 2, qc = lane & 3;
    #pragma unroll
    for (int im = 0; im < 4; im++) {
        #pragma unroll
        for (int jn = 0; jn < 4; jn++) {
            int row = row0 + wm + im * 16 + qr;
            int col = col0 + wn + jn * 8 + 2 * qc;
            float b0v = bias[col], b1v = bias[col + 1];
            float2 o0 = make_float2(acc[im][jn][0] * inv32 + b0v,
                                    acc[im][jn][1] * inv32 + b1v);
            float2 o1 = make_float2(acc[im][jn][2] * inv32 + b0v,
                                    acc[im][jn][3] * inv32 + b1v);
            *(float2*)&C[(size_t)row * N + col] = o0;
            *(float2*)&C[(size_t)(row + 8) * N + col] = o1;
        }
    }
}

// ====== Flash attention: 128-row q tiles, QK bf16 3-term, PV fp16 1-term =====
#define LQ 136

__global__ __launch_bounds__(256) void flash_tc() {
    extern __shared__ __nv_bfloat16 smb[];
    __nv_bfloat16* Qh = smb;
    __nv_bfloat16* Ql = Qh + 128 * LQ;
    __nv_bfloat16* Kh = Ql + 128 * LQ;
    __nv_bfloat16* Kl = Kh + 64 * LQ;
    __half*        Vh = (__half*)(Kl + 64 * LQ);

    const int tid  = threadIdx.x;
    const int lane = tid & 31;
    const int warp = tid >> 5;
    const int qtile = gridDim.z - 1 - blockIdx.z;
    const int h  = blockIdx.x;
    const int b  = blockIdx.y;
    const int g  = h / (H / G);
    const int q0 = qtile * 128;
    const int wm = warp * 16;

    const unsigned qBH = (unsigned)__cvta_generic_to_shared(Qh);
    const unsigned qBL = (unsigned)__cvta_generic_to_shared(Ql);
    const unsigned kBH = (unsigned)__cvta_generic_to_shared(Kh);
    const unsigned kBL = (unsigned)__cvta_generic_to_shared(Kl);
    const unsigned vBH = (unsigned)__cvta_generic_to_shared(Vh);

    #pragma unroll
    for (int it = 0; it < 8; it++) {
        int i4 = tid + it * 256;
        int r  = i4 >> 4;
        int c8 = (i4 & 15) * 8;
        size_t gi = ((size_t)(b * H + h) * S + q0 + r) * HD + c8;
        *(uint4*)&Qh[r * LQ + c8] = *(const uint4*)&g_qsh[gi];
        *(uint4*)&Ql[r * LQ + c8] = *(const uint4*)&g_qsl[gi];
    }

    const int gid = lane >> 2, tig = lane & 3;
    const int row0g = q0 + wm + gid;
    const int row1g = row0g + 8;
    const int wmaxrow = q0 + wm + 15;

    float rm0 = -1e30f, rm1 = -1e30f, rl0 = 0.0f, rl1 = 0.0f;
    float oacc[16][4] = {};

    const int NKT = 2 * qtile + 2;
    for (int kt = 0; kt < NKT; kt++) {
        const int k0 = kt * 64;
        __syncthreads();
        #pragma unroll
        for (int it = 0; it < 4; it++) {
            int i4 = tid + it * 256;
            int r  = i4 >> 4;
            int c8 = (i4 & 15) * 8;
            size_t gi = ((size_t)(b * G + g) * S + k0 + r) * HD + c8;
            unsigned so = r * LQ + c8;
            *(uint4*)&Kh[so] = *(const uint4*)&g_ksh[gi];
            *(uint4*)&Kl[so] = *(const uint4*)&g_ksl[gi];
            *(uint4*)&Vh[so] = *(const uint4*)&g_vsh[gi];
        }
        __syncthreads();

        if (k0 > wmaxrow) continue;

        // ---- S = Q @ K^T (bf16 3-term, nb-paired) ----
        float sacc[8][4] = {};
        #pragma unroll
        for (int ks = 0; ks < 8; ks++) {
            unsigned ah[4], al[4];
            unsigned offa = ((wm + (lane & 15)) * LQ + ks * 16 + (lane >> 4) * 8) * 2;
            LDSM4(ah, qBH + offa);
            LDSM4(al, qBL + offa);
            #pragma unroll
            for (int np = 0; np < 2; np++) {
                unsigned kh0[4], kl0[4], kh1[4], kl1[4];
                unsigned ob0 = (((2 * np + 0) * 16 + (lane >> 4) * 8 + (lane & 7)) * LQ +
                                ks * 16 + ((lane >> 3) & 1) * 8) * 2;
                unsigned ob1 = (((2 * np + 1) * 16 + (lane >> 4) * 8 + (lane & 7)) * LQ +
                                ks * 16 + ((lane >> 3) & 1) * 8) * 2;
                LDSM4(kh0, kBH + ob0);
                LDSM4(kl0, kBL + ob0);
                LDSM4(kh1, kBH + ob1);
                LDSM4(kl1, kBL + ob1);
                MMA16816(sacc[4 * np + 0], ah, kh0[0], kh0[1]);
                MMA16816(sacc[4 * np + 1], ah, kh0[2], kh0[3]);
                MMA16816(sacc[4 * np + 2], ah, kh1[0], kh1[1]);
                MMA16816(sacc[4 * np + 3], ah, kh1[2], kh1[3]);
                MMA16816(sacc[4 * np + 0], ah, kl0[0], kl0[1]);
                MMA16816(sacc[4 * np + 1], ah, kl0[2], kl0[3]);
                MMA16816(sacc[4 * np + 2], ah, kl1[0], kl1[1]);
                MMA16816(sacc[4 * np + 3], ah, kl1[2], kl1[3]);
                MMA16816(sacc[4 * np + 0], al, kh0[0], kh0[1]);
                MMA16816(sacc[4 * np + 1], al, kh0[2], kh0[3]);
                MMA16816(sacc[4 * np + 2], al, kh1[0], kh1[1]);
                MMA16816(sacc[4 * np + 3], al, kh1[2], kh1[3]);
            }
        }

        if (k0 + 63 > row0g) {
            #pragma unroll
            for (int nt = 0; nt < 8; nt++) {
                int colg = k0 + nt * 8 + 2 * tig;
                if (colg > row0g)     sacc[nt][0] = -1e30f;
                if (colg + 1 > row0g) sacc[nt][1] = -1e30f;
                if (colg > row1g)     sacc[nt][2] = -1e30f;
                if (colg + 1 > row1g) sacc[nt][3] = -1e30f;
            }
        }

        // ---- online softmax ----
        float mx0 = rm0, mx1 = rm1;
        #pragma unroll
        for (int nt = 0; nt < 8; nt++) {
            mx0 = fmaxf(mx0, fmaxf(sacc[nt][0], sacc[nt][1]));
            mx1 = fmaxf(mx1, fmaxf(sacc[nt][2], sacc[nt][3]));
        }
        mx0 = fmaxf(mx0, __shfl_xor_sync(0xffffffff, mx0, 1));
        mx0 = fmaxf(mx0, __shfl_xor_sync(0xffffffff, mx0, 2));
        mx1 = fmaxf(mx1, __shfl_xor_sync(0xffffffff, mx1, 1));
        mx1 = fmaxf(mx1, __shfl_xor_sync(0xffffffff, mx1, 2));
        float sc0 = __expf(rm0 - mx0);
        float sc1 = __expf(rm1 - mx1);
        rm0 = mx0; rm1 = mx1;
        float sum0 = 0.0f, sum1 = 0.0f;
        #pragma unroll
        for (int nt = 0; nt < 8; nt++) {
            sacc[nt][0] = __expf(sacc[nt][0] - mx0);
            sacc[nt][1] = __expf(sacc[nt][1] - mx0);
            sacc[nt][2] = __expf(sacc[nt][2] - mx1);
            sacc[nt][3] = __expf(sacc[nt][3] - mx1);
            sum0 += sacc[nt][0] + sacc[nt][1];
            sum1 += sacc[nt][2] + sacc[nt][3];
        }
        sum0 += __shfl_xor_sync(0xffffffff, sum0, 1);
        sum0 += __shfl_xor_sync(0xffffffff, sum0, 2);
        sum1 += __shfl_xor_sync(0xffffffff, sum1, 1);
        sum1 += __shfl_xor_sync(0xffffffff, sum1, 2);
        rl0 = rl0 * sc0 + sum0;
        rl1 = rl1 * sc1 + sum1;
        #pragma unroll
        for (int nt = 0; nt < 16; nt++) {
            oacc[nt][0] *= sc0; oacc[nt][1] *= sc0;
            oacc[nt][2] *= sc1; oacc[nt][3] *= sc1;
        }

        // ---- O += P @ V (fp16 single-term) ----
        #pragma unroll
        for (int j = 0; j < 4; j++) {
            unsigned ph[4];
            ph[0] = packh2(sacc[2 * j][0],     sacc[2 * j][1]);
            ph[1] = packh2(sacc[2 * j][2],     sacc[2 * j][3]);
            ph[2] = packh2(sacc[2 * j + 1][0], sacc[2 * j + 1][1]);
            ph[3] = packh2(sacc[2 * j + 1][2], sacc[2 * j + 1][3]);
            #pragma unroll
            for (int nb = 0; nb < 8; nb++) {
                unsigned vh4[4];
                unsigned offv = ((j * 16 + (lane & 7) + ((lane >> 3) & 1) * 8) * LQ +
                                 nb * 16 + (lane >> 4) * 8) * 2;
                LDSM4T(vh4, vBH + offv);
                MMA16816H(oacc[2 * nb + 0], ph, vh4[0], vh4[1]);
                MMA16816H(oacc[2 * nb + 1], ph, vh4[2], vh4[3]);
            }
        }
    }

    // ---- finalize: divide by l, store fp16 single ----
    float li0 = 1.0f / rl0, li1 = 1.0f / rl1;
    size_t or0 = (size_t)(b * S + row0g) * (H * HD) + h * HD;
    size_t or1 = (size_t)(b * S + row1g) * (H * HD) + h * HD;
    #pragma unroll
    for (int nt = 0; nt < 16; nt++) {
        int col = nt * 8 + 2 * tig;
        *(unsigned*)&g_ah[or0 + col] = packh2(oacc[nt][0] * li0, oacc[nt][1] * li0);
        *(unsigned*)&g_ah[or1 + col] = packh2(oacc[nt][2] * li1, oacc[nt][3] * li1);
    }
}

// =============================== launch ======================================
extern "C" void kernel_launch(void* const* d_in, const int* in_sizes, int n_in,
                              void* d_out, int out_size) {
    const float* x  = (const float*)d_in[0];
    const float* Wq = (const float*)d_in[1];
    const float* bq = (const float*)d_in[2];
    const float* Wk = (const float*)d_in[3];
    const float* bk = (const float*)d_in[4];
    const float* Wv = (const float*)d_in[5];
    const float* bv = (const float*)d_in[6];
    const float* Wo = (const float*)d_in[7];
    const float* bo = (const float*)d_in[8];
    float* out = (float*)d_out;

    __nv_bfloat16 *xh, *xl, *wqh, *wql;
    __half *woh, *ah;
    float *bqkv;
    cudaGetSymbolAddress((void**)&xh, g_xh);
    cudaGetSymbolAddress((void**)&xl, g_xl);
    cudaGetSymbolAddress((void**)&wqh, g_wqh);
    cudaGetSymbolAddress((void**)&wql, g_wql);
    cudaGetSymbolAddress((void**)&woh, g_woh);
    cudaGetSymbolAddress((void**)&ah, g_ah);
    cudaGetSymbolAddress((void**)&bqkv, g_bqkv);

    const int M = B * S;  // 8192

    convert_all<<<(CTOT + 255) / 256, 256>>>(x, Wq, Wk, Wv, Wo, bq, bk, bv);

    size_t gsm = (size_t)2 * ST_EL * sizeof(__nv_bfloat16);  // 75776 B (2-stage, 2 CTAs/SM)
    cudaFuncSetAttribute(gemm_qkv_fused, cudaFuncAttributeMaxDynamicSharedMemorySize, (int)gsm);
    size_t gsmh = (size_t)3 * STH_EL * sizeof(__half);       // 56832 B
    cudaFuncSetAttribute(gemm_out_h, cudaFuncAttributeMaxDynamicSharedMemorySize, (int)gsmh);

    // ---- fused QKV projection + bias + RoPE + split ----
    gemm_qkv_fused<<<dim3(NQKV / 128, M / 128), 256, gsm>>>(xh, xl, wqh, wql, bqkv);

    // ---- flash attention (128-row q tiles, heavy-first via z) ----
    size_t smem = (size_t)(2 * 128 + 3 * 64) * LQ * sizeof(__nv_bfloat16);  // 121856 B
    cudaFuncSetAttribute(flash_tc, cudaFuncAttributeMaxDynamicSharedMemorySize, (int)smem);
    flash_tc<<<dim3(H, B, S / 128), 256, smem>>>();

    // ---- output projection (fp16 single-term) ----
    gemm_out_h<<<dim3(D / 128, M / 128), 256, gsmh>>>(
        ah, woh, bo, out, M, D, H * HD);
}

// round 15
// speedup vs baseline: 1.1380x; 1.0082x over previous
#include <cuda_runtime.h>
#include <cuda_bf16.h>
#include <cuda_fp16.h>
#include <math.h>

#define B 4
#define S 2048
#define D 2048
#define H 16
#define G 4
#define HD 128
#define NQKV 3072   // packed q(2048) | k(512) | v(512)

// ------------------------- scratch (device globals, no allocs) --------------
__device__ __nv_bfloat16 g_xh[(size_t)B * S * D];
__device__ __nv_bfloat16 g_xl[(size_t)B * S * D];
__device__ __nv_bfloat16 g_wqh[(size_t)D * NQKV];          // packed Wqkv hi [k][n]
__device__ __nv_bfloat16 g_wql[(size_t)D * NQKV];
__device__ __half        g_woh[(size_t)H * HD * D];        // Wo*32 (fp16 single)
__device__ __half        g_ah[(size_t)B * S * H * HD];     // attn out (fp16 single)
__device__ float         g_bqkv[NQKV];
__device__ float2        g_rope[(size_t)S * 64];           // (cos,sin) per (s, freq)
// pre-split, roped operands for flash
__device__ __nv_bfloat16 g_qsh[(size_t)B * H * S * HD];
__device__ __nv_bfloat16 g_qsl[(size_t)B * H * S * HD];
__device__ __nv_bfloat16 g_ksh[(size_t)B * G * S * HD];
__device__ __nv_bfloat16 g_ksl[(size_t)B * G * S * HD];
__device__ __half        g_vsh[(size_t)B * G * S * HD];

// ============================ shared PTX helpers =============================
#define LDSM4(R, addr)                                                        \
    asm volatile("ldmatrix.sync.aligned.m8n8.x4.shared.b16 {%0,%1,%2,%3}, [%4];" \
                 : "=r"(R[0]), "=r"(R[1]), "=r"(R[2]), "=r"(R[3]) : "r"(addr))
#define LDSM4T(R, addr)                                                       \
    asm volatile("ldmatrix.sync.aligned.m8n8.x4.trans.shared.b16 {%0,%1,%2,%3}, [%4];" \
                 : "=r"(R[0]), "=r"(R[1]), "=r"(R[2]), "=r"(R[3]) : "r"(addr))
#define MMA16816(d, a, b0v, b1v)                                              \
    asm volatile("mma.sync.aligned.m16n8k16.row.col.f32.bf16.bf16.f32 "       \
                 "{%0,%1,%2,%3},{%4,%5,%6,%7},{%8,%9},{%0,%1,%2,%3};"         \
                 : "+f"(d[0]), "+f"(d[1]), "+f"(d[2]), "+f"(d[3])             \
                 : "r"(a[0]), "r"(a[1]), "r"(a[2]), "r"(a[3]),                \
                   "r"(b0v), "r"(b1v))
#define MMA16816H(d, a, b0v, b1v)                                             \
    asm volatile("mma.sync.aligned.m16n8k16.row.col.f32.f16.f16.f32 "         \
                 "{%0,%1,%2,%3},{%4,%5,%6,%7},{%8,%9},{%0,%1,%2,%3};"         \
                 : "+f"(d[0]), "+f"(d[1]), "+f"(d[2]), "+f"(d[3])             \
                 : "r"(a[0]), "r"(a[1]), "r"(a[2]), "r"(a[3]),                \
                   "r"(b0v), "r"(b1v))
#define CP16(smaddr, gptr)                                                    \
    asm volatile("cp.async.cg.shared.global [%0], [%1], 16;" :: "r"(smaddr), "l"(gptr))
#define CP_COMMIT asm volatile("cp.async.commit_group;")

__device__ __forceinline__ void split2(float x, float y,
                                       unsigned& hi, unsigned& lo) {
    __nv_bfloat16 hx = __float2bfloat16_rn(x);
    __nv_bfloat16 hy = __float2bfloat16_rn(y);
    float rx = x - __bfloat162float(hx);
    float ry = y - __bfloat162float(hy);
    __nv_bfloat16 lx = __float2bfloat16_rn(rx);
    __nv_bfloat16 ly = __float2bfloat16_rn(ry);
    __nv_bfloat162 h2 = __nv_bfloat162(hx, hy);
    __nv_bfloat162 l2 = __nv_bfloat162(lx, ly);
    hi = *(unsigned*)&h2;
    lo = *(unsigned*)&l2;
}

__device__ __forceinline__ unsigned packh2(float x, float y) {
    __half2 h = __floats2half2_rn(x, y);
    return *(unsigned*)&h;
}

// ================= ONE fused conversion / packing / table kernel =============
#define CN0 4194304
#define CN1 1048576
#define CN2 262144
#define CN3 262144
#define CN4 1048576
#define CN5 3072
#define CN6 131072
#define CTOT (CN0 + CN1 + CN2 + CN3 + CN4 + CN5 + CN6)

__global__ void convert_all(const float* __restrict__ x,
                            const float* __restrict__ Wq,
                            const float* __restrict__ Wk,
                            const float* __restrict__ Wv,
                            const float* __restrict__ Wo,
                            const float* __restrict__ bq,
                            const float* __restrict__ bk,
                            const float* __restrict__ bv) {
    long i = (long)blockIdx.x * blockDim.x + threadIdx.x;
    if (i < CN0) {
        float4 v = ((const float4*)x)[i];
        uint2 h, l;
        split2(v.x, v.y, h.x, l.x);
        split2(v.z, v.w, h.y, l.y);
        ((uint2*)g_xh)[i] = h;
        ((uint2*)g_xl)[i] = l;
    } else if (i < CN0 + CN1 + CN2 + CN3) {
        long j;
        int srcN, off;
        const float* src;
        if (i < CN0 + CN1)      { j = i - CN0;               srcN = 2048; off = 0;    src = Wq; }
        else if (i < CN0 + CN1 + CN2) { j = i - CN0 - CN1;   srcN = 512;  off = 2048; src = Wk; }
        else                    { j = i - CN0 - CN1 - CN2;   srcN = 512;  off = 2560; src = Wv; }
        int rw = srcN >> 2;
        int r = (int)(j / rw), c = (int)(j % rw) * 4;
        float4 v = *(const float4*)&src[(size_t)r * srcN + c];
        uint2 h, l;
        split2(v.x, v.y, h.x, l.x);
        split2(v.z, v.w, h.y, l.y);
        size_t d = (size_t)r * NQKV + off + c;
        *(uint2*)&g_wqh[d] = h;
        *(uint2*)&g_wql[d] = l;
    } else if (i < CN0 + CN1 + CN2 + CN3 + CN4) {
        long j = i - (CN0 + CN1 + CN2 + CN3);
        float4 v = ((const float4*)Wo)[j];
        uint2 h;
        h.x = packh2(v.x * 32.0f, v.y * 32.0f);
        h.y = packh2(v.z * 32.0f, v.w * 32.0f);
        ((uint2*)g_woh)[j] = h;
    } else if (i < CN0 + CN1 + CN2 + CN3 + CN4 + CN5) {
        int j = (int)(i - (CN0 + CN1 + CN2 + CN3 + CN4));
        g_bqkv[j] = (j < 2048) ? bq[j] : (j < 2560) ? bk[j - 2048] : bv[j - 2560];
    } else {
        int j = (int)(i - (CN0 + CN1 + CN2 + CN3 + CN4 + CN5));
        int s = j >> 6, f = j & 63;
        float inv_freq = powf(10000.0f, -(float)f / 64.0f);
        float ang = (float)s * inv_freq;
        g_rope[j] = make_float2(cosf(ang), sinf(ang));
    }
}

// ======================== bf16 3-term GEMM mainloop ==========================
#define LDA 40
#define LDB 136
#define ST_EL 18944   // per-stage smem elements: 2*128*40 + 2*32*136

struct GemmAcc { float a[4][4][4]; };

// 2-stage cp.async pipeline, term-major mma.
__device__ __forceinline__ void gemm_mainloop2(
    const __nv_bfloat16* __restrict__ Ahg, const __nv_bfloat16* __restrict__ Alg,
    const __nv_bfloat16* __restrict__ Bhg, const __nv_bfloat16* __restrict__ Blg,
    int K, int N, int row0, int col0, unsigned smBase, GemmAcc& acc) {
    const int tid = threadIdx.x;
    const int lane = tid & 31;
    const int warp = tid >> 5;
    const int wm = (warp >> 2) * 64;
    const int wn = (warp & 3) * 32;
    const int NT = K / 32;

    auto issue = [&](int st, int k0) {
        unsigned sb = smBase + st * (ST_EL * 2);
        #pragma unroll
        for (int j = 0; j < 2; j++) {
            int c = tid + j * 256;
            int r = c >> 2, c8 = (c & 3) * 8;
            unsigned so = (unsigned)(r * LDA + c8) * 2;
            CP16(sb + so, &Ahg[(size_t)(row0 + r) * K + k0 + c8]);
            CP16(sb + 10240 + so, &Alg[(size_t)(row0 + r) * K + k0 + c8]);
        }
        #pragma unroll
        for (int j = 0; j < 2; j++) {
            int c = tid + j * 256;
            int r = c >> 4, c8 = (c & 15) * 8;
            unsigned so = (unsigned)(r * LDB + c8) * 2;
            CP16(sb + 20480 + so, &Bhg[(size_t)(k0 + r) * N + col0 + c8]);
            CP16(sb + 29184 + so, &Blg[(size_t)(k0 + r) * N + col0 + c8]);
        }
    };

    issue(0, 0);
    CP_COMMIT;

    for (int it = 0; it < NT; it++) {
        if (it + 1 < NT) {
            issue((it + 1) & 1, (it + 1) * 32);
            CP_COMMIT;
            asm volatile("cp.async.wait_group 1;");
        } else {
            asm volatile("cp.async.wait_group 0;");
        }
        __syncthreads();

        unsigned sb = smBase + (it & 1) * (ST_EL * 2);
        const unsigned aBaseH = sb, aBaseL = sb + 10240;
        const unsigned bBaseH = sb + 20480, bBaseL = sb + 29184;

        #pragma unroll
        for (int ks = 0; ks < 2; ks++) {
            unsigned ah[4][4], al[4][4];
            #pragma unroll
            for (int im = 0; im < 4; im++) {
                unsigned off =
                    ((wm + im * 16 + (lane & 15)) * LDA + ks * 16 + (lane >> 4) * 8) * 2;
                LDSM4(ah[im], aBaseH + off);
                LDSM4(al[im], aBaseL + off);
            }
            int krow = ks * 16 + (lane & 7) + ((lane >> 3) & 1) * 8;
            #pragma unroll
            for (int pr = 0; pr < 2; pr++) {
                unsigned bh[4], bl[4];
                unsigned off = (krow * LDB + wn + pr * 16 + (lane >> 4) * 8) * 2;
                LDSM4T(bh, bBaseH + off);
                LDSM4T(bl, bBaseL + off);
                #pragma unroll
                for (int im = 0; im < 4; im++)
                    MMA16816(acc.a[im][pr * 2 + 0], ah[im], bh[0], bh[1]);
                #pragma unroll
                for (int im = 0; im < 4; im++)
                    MMA16816(acc.a[im][pr * 2 + 1], ah[im], bh[2], bh[3]);
                #pragma unroll
                for (int im = 0; im < 4; im++)
                    MMA16816(acc.a[im][pr * 2 + 0], ah[im], bl[0], bl[1]);
                #pragma unroll
                for (int im = 0; im < 4; im++)
                    MMA16816(acc.a[im][pr * 2 + 1], ah[im], bl[2], bl[3]);
                #pragma unroll
                for (int im = 0; im < 4; im++)
                    MMA16816(acc.a[im][pr * 2 + 0], al[im], bh[0], bh[1]);
                #pragma unroll
                for (int im = 0; im < 4; im++)
                    MMA16816(acc.a[im][pr * 2 + 1], al[im], bh[2], bh[3]);
            }
        }
        __syncthreads();
    }
}

// ============= QKV GEMM with fused bias + RoPE + hi/lo split epilogue ========
#define STF 132   // fp32 smem stride for epilogue tile

__global__ __launch_bounds__(256, 2) void gemm_qkv_fused(
    const __nv_bfloat16* __restrict__ Ahg, const __nv_bfloat16* __restrict__ Alg,
    const __nv_bfloat16* __restrict__ Bhg, const __nv_bfloat16* __restrict__ Blg,
    const float* __restrict__ bias) {
    extern __shared__ __nv_bfloat16 smem[];
    const unsigned smBase = (unsigned)__cvta_generic_to_shared(smem);

    const int tid = threadIdx.x;
    const int lane = tid & 31;
    const int warp = tid >> 5;
    const int wm = (warp >> 2) * 64;
    const int wn = (warp & 3) * 32;
    const int row0 = blockIdx.y * 128;
    const int col0 = blockIdx.x * 128;

    GemmAcc acc = {};
    gemm_mainloop2(Ahg, Alg, Bhg, Blg, D, NQKV, row0, col0, smBase, acc);

    // ---- stage fp32 tile (with bias) in smem ----
    float* st = (float*)smem;
    const int qr = lane >> 2, qc = lane & 3;
    #pragma unroll
    for (int im = 0; im < 4; im++) {
        #pragma unroll
        for (int jn = 0; jn < 4; jn++) {
            int rr = wm + im * 16 + qr;
            int cc = wn + jn * 8 + 2 * qc;
            float b0v = bias[col0 + cc], b1v = bias[col0 + cc + 1];
            st[rr * STF + cc]           = acc.a[im][jn][0] + b0v;
            st[rr * STF + cc + 1]       = acc.a[im][jn][1] + b1v;
            st[(rr + 8) * STF + cc]     = acc.a[im][jn][2] + b0v;
            st[(rr + 8) * STF + cc + 1] = acc.a[im][jn][3] + b1v;
        }
    }
    __syncthreads();

    const int tile = col0 >> 7;      // head tile: 0-15 q, 16-19 k, 20-23 v
    const int bb = row0 >> 11;
    const float scale = 0.08838834764831845f;

    if (tile < 20) {   // q or k: rope (table) + split (bf16)
        bool isq = tile < 16;
        int hh = isq ? tile : tile - 16;
        int nh = isq ? H : G;
        __nv_bfloat16* dh = isq ? g_qsh : g_ksh;
        __nv_bfloat16* dl = isq ? g_qsl : g_ksl;
        float sc = isq ? scale : 1.0f;
        #pragma unroll 4
        for (int t = 0; t < 16; t++) {
            int idx = tid + t * 256;
            int r = idx >> 5;
            int i2 = (idx & 31) * 2;
            int s = (row0 + r) & (S - 1);
            float a0 = st[r * STF + i2],      a1 = st[r * STF + i2 + 1];
            float c0 = st[r * STF + i2 + 64], c1 = st[r * STF + i2 + 65];
            float4 tcs = *(const float4*)&g_rope[(size_t)s * 64 + i2];
            float o10 = (a0 * tcs.x - c0 * tcs.y) * sc;
            float o11 = (a1 * tcs.z - c1 * tcs.w) * sc;
            float o20 = (c0 * tcs.x + a0 * tcs.y) * sc;
            float o21 = (c1 * tcs.z + a1 * tcs.w) * sc;
            unsigned h1, l1, h2, l2;
            split2(o10, o11, h1, l1);
            split2(o20, o21, h2, l2);
            size_t dst = ((size_t)(bb * nh + hh) * S + s) * HD + i2;
            *(unsigned*)&dh[dst] = h1;
            *(unsigned*)&dl[dst] = l1;
            *(unsigned*)&dh[dst + 64] = h2;
            *(unsigned*)&dl[dst + 64] = l2;
        }
    } else {           // v: single fp16
        int gg = tile - 20;
        #pragma unroll 4
        for (int t = 0; t < 32; t++) {
            int idx = tid + t * 256;
            int r = idx >> 6;
            int i2 = (idx & 63) * 2;
            int s = (row0 + r) & (S - 1);
            float v0 = st[r * STF + i2], v1 = st[r * STF + i2 + 1];
            size_t dst = ((size_t)(bb * G + gg) * S + s) * HD + i2;
            *(unsigned*)&g_vsh[dst] = packh2(v0, v1);
        }
    }
}

// ============ output projection: A fp16 single x W fp16 single ===============
#define STH_EL 9472   // per-stage elements: 128*40 + 32*136

__global__ __launch_bounds__(256) void gemm_out_h(
    const __half* __restrict__ Ag, const __half* __restrict__ Bg,
    const float* __restrict__ bias, float* __restrict__ C,
    int M, int N, int K) {
    extern __shared__ __nv_bfloat16 smemb[];
    __half* smem = (__half*)smemb;
    const unsigned smBase = (unsigned)__cvta_generic_to_shared(smem);

    const int tid = threadIdx.x;
    const int lane = tid & 31;
    const int warp = tid >> 5;
    const int wm = (warp >> 2) * 64;
    const int wn = (warp & 3) * 32;
    const int row0 = blockIdx.y * 128;
    const int col0 = blockIdx.x * 128;
    const int NT = K / 32;

    float acc[4][4][4] = {};

    auto issue = [&](int st, int k0) {
        unsigned sb = smBase + st * (STH_EL * 2);
        #pragma unroll
        for (int j = 0; j < 2; j++) {
            int c = tid + j * 256;
            int r = c >> 2, c8 = (c & 3) * 8;
            unsigned so = (unsigned)(r * LDA + c8) * 2;
            CP16(sb + so, &Ag[(size_t)(row0 + r) * K + k0 + c8]);
        }
        #pragma unroll
        for (int j = 0; j < 2; j++) {
            int c = tid + j * 256;
            int r = c >> 4, c8 = (c & 15) * 8;
            unsigned so = (unsigned)(r * LDB + c8) * 2;
            CP16(sb + 10240 + so, &Bg[(size_t)(k0 + r) * N + col0 + c8]);
        }
    };

    issue(0, 0);
    CP_COMMIT;
    issue(1, 32);
    CP_COMMIT;

    for (int it = 0; it < NT; it++) {
        if (it == NT - 1) {
            asm volatile("cp.async.wait_group 0;");
        } else {
            asm volatile("cp.async.wait_group 1;");
        }
        __syncthreads();
        if (it + 2 < NT) {
            issue((it + 2) % 3, (it + 2) * 32);
            CP_COMMIT;
        }

        unsigned sb = smBase + (it % 3) * (STH_EL * 2);
        const unsigned aBase = sb;
        const unsigned bBase = sb + 10240;

        #pragma unroll
        for (int ks = 0; ks < 2; ks++) {
            unsigned ah[4][4];
            #pragma unroll
            for (int im = 0; im < 4; im++) {
                unsigned off =
                    ((wm + im * 16 + (lane & 15)) * LDA + ks * 16 + (lane >> 4) * 8) * 2;
                LDSM4(ah[im], aBase + off);
            }
            int krow = ks * 16 + (lane & 7) + ((lane >> 3) & 1) * 8;
            #pragma unroll
            for (int pr = 0; pr < 2; pr++) {
                unsigned bh[4];
                unsigned off = (krow * LDB + wn + pr * 16 + (lane >> 4) * 8) * 2;
                LDSM4T(bh, bBase + off);
                #pragma unroll
                for (int im = 0; im < 4; im++) {
                    MMA16816H(acc[im][pr * 2 + 0], ah[im], bh[0], bh[1]);
                    MMA16816H(acc[im][pr * 2 + 1], ah[im], bh[2], bh[3]);
                }
            }
        }
    }

    const float inv32 = 1.0f / 32.0f;
    const int qr = lane >> 2, qc = lane & 3;
    #pragma unroll
    for (int im = 0; im < 4; im++) {
        #pragma unroll
        for (int jn = 0; jn < 4; jn++) {
            int row = row0 + wm + im * 16 + qr;
            int col = col0 + wn + jn * 8 + 2 * qc;
            float b0v = bias[col], b1v = bias[col + 1];
            float2 o0 = make_float2(acc[im][jn][0] * inv32 + b0v,
                                    acc[im][jn][1] * inv32 + b1v);
            float2 o1 = make_float2(acc[im][jn][2] * inv32 + b0v,
                                    acc[im][jn][3] * inv32 + b1v);
            *(float2*)&C[(size_t)row * N + col] = o0;
            *(float2*)&C[(size_t)(row + 8) * N + col] = o1;
        }
    }
}

// == Flash attention: 128-row q tiles, cp.async double-buffered K/V tiles =====
#define LQ 136
#define FST_B (3 * 64 * LQ * 2)   // bytes per K/V stage (Kh,Kl,Vh)

__global__ __launch_bounds__(256) void flash_tc() {
    extern __shared__ __nv_bfloat16 smb[];
    __nv_bfloat16* Qh = smb;
    __nv_bfloat16* Ql = Qh + 128 * LQ;
    // K/V stages start after Q
    const unsigned smBase = (unsigned)__cvta_generic_to_shared(smb);
    const unsigned kvBase = smBase + 2 * 128 * LQ * 2;

    const int tid  = threadIdx.x;
    const int lane = tid & 31;
    const int warp = tid >> 5;
    const int qtile = gridDim.z - 1 - blockIdx.z;
    const int h  = blockIdx.x;
    const int b  = blockIdx.y;
    const int g  = h / (H / G);
    const int q0 = qtile * 128;
    const int wm = warp * 16;

    const unsigned qBH = smBase;
    const unsigned qBL = smBase + 128 * LQ * 2;

    // ---- cp.async one K/V stage ----
    auto kv_issue = [&](int st, int kt2) {
        int k0 = kt2 * 64;
        unsigned sb = kvBase + st * FST_B;
        #pragma unroll
        for (int it = 0; it < 4; it++) {
            int i4 = tid + it * 256;
            int r  = i4 >> 4;
            int c8 = (i4 & 15) * 8;
            size_t gi = ((size_t)(b * G + g) * S + k0 + r) * HD + c8;
            unsigned so = (unsigned)(r * LQ + c8) * 2;
            CP16(sb + so, g_ksh + gi);
            CP16(sb + 64 * LQ * 2 + so, g_ksl + gi);
            CP16(sb + 128 * LQ * 2 + so, g_vsh + gi);
        }
    };

    kv_issue(0, 0);
    CP_COMMIT;

    // ---- load Q tile (pre-split, pre-scaled, roped) ----
    #pragma unroll
    for (int it = 0; it < 8; it++) {
        int i4 = tid + it * 256;
        int r  = i4 >> 4;
        int c8 = (i4 & 15) * 8;
        size_t gi = ((size_t)(b * H + h) * S + q0 + r) * HD + c8;
        *(uint4*)&Qh[r * LQ + c8] = *(const uint4*)&g_qsh[gi];
        *(uint4*)&Ql[r * LQ + c8] = *(const uint4*)&g_qsl[gi];
    }

    const int gid = lane >> 2, tig = lane & 3;
    const int row0g = q0 + wm + gid;
    const int row1g = row0g + 8;
    const int wmaxrow = q0 + wm + 15;

    float rm0 = -1e30f, rm1 = -1e30f, rl0 = 0.0f, rl1 = 0.0f;
    float oacc[16][4] = {};

    const int NKT = 2 * qtile + 2;
    for (int kt = 0; kt < NKT; kt++) {
        const int k0 = kt * 64;
        if (kt + 1 < NKT) {
            kv_issue((kt + 1) & 1, kt + 1);
            CP_COMMIT;
            asm volatile("cp.async.wait_group 1;");
        } else {
            asm volatile("cp.async.wait_group 0;");
        }
        __syncthreads();

        unsigned sb = kvBase + (kt & 1) * FST_B;
        const unsigned kBH = sb;
        const unsigned kBL = sb + 64 * LQ * 2;
        const unsigned vBH = sb + 128 * LQ * 2;

        if (k0 <= wmaxrow) {
            // ---- S = Q @ K^T (bf16 3-term, nb-paired) ----
            float sacc[8][4] = {};
            #pragma unroll
            for (int ks = 0; ks < 8; ks++) {
                unsigned ah[4], al[4];
                unsigned offa = ((wm + (lane & 15)) * LQ + ks * 16 + (lane >> 4) * 8) * 2;
                LDSM4(ah, qBH + offa);
                LDSM4(al, qBL + offa);
                #pragma unroll
                for (int np = 0; np < 2; np++) {
                    unsigned kh0[4], kl0[4], kh1[4], kl1[4];
                    unsigned ob0 = (((2 * np + 0) * 16 + (lane >> 4) * 8 + (lane & 7)) * LQ +
                                    ks * 16 + ((lane >> 3) & 1) * 8) * 2;
                    unsigned ob1 = (((2 * np + 1) * 16 + (lane >> 4) * 8 + (lane & 7)) * LQ +
                                    ks * 16 + ((lane >> 3) & 1) * 8) * 2;
                    LDSM4(kh0, kBH + ob0);
                    LDSM4(kl0, kBL + ob0);
                    LDSM4(kh1, kBH + ob1);
                    LDSM4(kl1, kBL + ob1);
                    MMA16816(sacc[4 * np + 0], ah, kh0[0], kh0[1]);
                    MMA16816(sacc[4 * np + 1], ah, kh0[2], kh0[3]);
                    MMA16816(sacc[4 * np + 2], ah, kh1[0], kh1[1]);
                    MMA16816(sacc[4 * np + 3], ah, kh1[2], kh1[3]);
                    MMA16816(sacc[4 * np + 0], ah, kl0[0], kl0[1]);
                    MMA16816(sacc[4 * np + 1], ah, kl0[2], kl0[3]);
                    MMA16816(sacc[4 * np + 2], ah, kl1[0], kl1[1]);
                    MMA16816(sacc[4 * np + 3], ah, kl1[2], kl1[3]);
                    MMA16816(sacc[4 * np + 0], al, kh0[0], kh0[1]);
                    MMA16816(sacc[4 * np + 1], al, kh0[2], kh0[3]);
                    MMA16816(sacc[4 * np + 2], al, kh1[0], kh1[1]);
                    MMA16816(sacc[4 * np + 3], al, kh1[2], kh1[3]);
                }
            }

            if (k0 + 63 > row0g) {
                #pragma unroll
                for (int nt = 0; nt < 8; nt++) {
                    int colg = k0 + nt * 8 + 2 * tig;
                    if (colg > row0g)     sacc[nt][0] = -1e30f;
                    if (colg + 1 > row0g) sacc[nt][1] = -1e30f;
                    if (colg > row1g)     sacc[nt][2] = -1e30f;
                    if (colg + 1 > row1g) sacc[nt][3] = -1e30f;
                }
            }

            // ---- online softmax ----
            float mx0 = rm0, mx1 = rm1;
            #pragma unroll
            for (int nt = 0; nt < 8; nt++) {
                mx0 = fmaxf(mx0, fmaxf(sacc[nt][0], sacc[nt][1]));
                mx1 = fmaxf(mx1, fmaxf(sacc[nt][2], sacc[nt][3]));
            }
            mx0 = fmaxf(mx0, __shfl_xor_sync(0xffffffff, mx0, 1));
            mx0 = fmaxf(mx0, __shfl_xor_sync(0xffffffff, mx0, 2));
            mx1 = fmaxf(mx1, __shfl_xor_sync(0xffffffff, mx1, 1));
            mx1 = fmaxf(mx1, __shfl_xor_sync(0xffffffff, mx1, 2));
            float sc0 = __expf(rm0 - mx0);
            float sc1 = __expf(rm1 - mx1);
            rm0 = mx0; rm1 = mx1;
            float sum0 = 0.0f, sum1 = 0.0f;
            #pragma unroll
            for (int nt = 0; nt < 8; nt++) {
                sacc[nt][0] = __expf(sacc[nt][0] - mx0);
                sacc[nt][1] = __expf(sacc[nt][1] - mx0);
                sacc[nt][2] = __expf(sacc[nt][2] - mx1);
                sacc[nt][3] = __expf(sacc[nt][3] - mx1);
                sum0 += sacc[nt][0] + sacc[nt][1];
                sum1 += sacc[nt][2] + sacc[nt][3];
            }
            sum0 += __shfl_xor_sync(0xffffffff, sum0, 1);
            sum0 += __shfl_xor_sync(0xffffffff, sum0, 2);
            sum1 += __shfl_xor_sync(0xffffffff, sum1, 1);
            sum1 += __shfl_xor_sync(0xffffffff, sum1, 2);
            rl0 = rl0 * sc0 + sum0;
            rl1 = rl1 * sc1 + sum1;
            #pragma unroll
            for (int nt = 0; nt < 16; nt++) {
                oacc[nt][0] *= sc0; oacc[nt][1] *= sc0;
                oacc[nt][2] *= sc1; oacc[nt][3] *= sc1;
            }

            // ---- O += P @ V (fp16 single-term) ----
            #pragma unroll
            for (int j = 0; j < 4; j++) {
                unsigned ph[4];
                ph[0] = packh2(sacc[2 * j][0],     sacc[2 * j][1]);
                ph[1] = packh2(sacc[2 * j][2],     sacc[2 * j][3]);
                ph[2] = packh2(sacc[2 * j + 1][0], sacc[2 * j + 1][1]);
                ph[3] = packh2(sacc[2 * j + 1][2], sacc[2 * j + 1][3]);
                #pragma unroll
                for (int nb = 0; nb < 8; nb++) {
                    unsigned vh4[4];
                    unsigned offv = ((j * 16 + (lane & 7) + ((lane >> 3) & 1) * 8) * LQ +
                                     nb * 16 + (lane >> 4) * 8) * 2;
                    LDSM4T(vh4, vBH + offv);
                    MMA16816H(oacc[2 * nb + 0], ph, vh4[0], vh4[1]);
                    MMA16816H(oacc[2 * nb + 1], ph, vh4[2], vh4[3]);
                }
            }
        }
        __syncthreads();   // protect buffer (kt&1) before it is re-issued
    }

    // ---- finalize: divide by l, store fp16 single ----
    float li0 = 1.0f / rl0, li1 = 1.0f / rl1;
    size_t or0 = (size_t)(b * S + row0g) * (H * HD) + h * HD;
    size_t or1 = (size_t)(b * S + row1g) * (H * HD) + h * HD;
    #pragma unroll
    for (int nt = 0; nt < 16; nt++) {
        int col = nt * 8 + 2 * tig;
        *(unsigned*)&g_ah[or0 + col] = packh2(oacc[nt][0] * li0, oacc[nt][1] * li0);
        *(unsigned*)&g_ah[or1 + col] = packh2(oacc[nt][2] * li1, oacc[nt][3] * li1);
    }
}

// =============================== launch ======================================
extern "C" void kernel_launch(void* const* d_in, const int* in_sizes, int n_in,
                              void* d_out, int out_size) {
    const float* x  = (const float*)d_in[0];
    const float* Wq = (const float*)d_in[1];
    const float* bq = (const float*)d_in[2];
    const float* Wk = (const float*)d_in[3];
    const float* bk = (const float*)d_in[4];
    const float* Wv = (const float*)d_in[5];
    const float* bv = (const float*)d_in[6];
    const float* Wo = (const float*)d_in[7];
    const float* bo = (const float*)d_in[8];
    float* out = (float*)d_out;

    __nv_bfloat16 *xh, *xl, *wqh, *wql;
    __half *woh, *ah;
    float *bqkv;
    cudaGetSymbolAddress((void**)&xh, g_xh);
    cudaGetSymbolAddress((void**)&xl, g_xl);
    cudaGetSymbolAddress((void**)&wqh, g_wqh);
    cudaGetSymbolAddress((void**)&wql, g_wql);
    cudaGetSymbolAddress((void**)&woh, g_woh);
    cudaGetSymbolAddress((void**)&ah, g_ah);
    cudaGetSymbolAddress((void**)&bqkv, g_bqkv);

    const int M = B * S;  // 8192

    convert_all<<<(CTOT + 255) / 256, 256>>>(x, Wq, Wk, Wv, Wo, bq, bk, bv);

    size_t gsm = (size_t)2 * ST_EL * sizeof(__nv_bfloat16);  // 75776 B
    cudaFuncSetAttribute(gemm_qkv_fused, cudaFuncAttributeMaxDynamicSharedMemorySize, (int)gsm);
    size_t gsmh = (size_t)3 * STH_EL * sizeof(__half);       // 56832 B
    cudaFuncSetAttribute(gemm_out_h, cudaFuncAttributeMaxDynamicSharedMemorySize, (int)gsmh);

    // ---- fused QKV projection + bias + RoPE + split ----
    gemm_qkv_fused<<<dim3(NQKV / 128, M / 128), 256, gsm>>>(xh, xl, wqh, wql, bqkv);

    // ---- flash attention (double-buffered K/V) ----
    size_t smem = (size_t)(2 * 128 * LQ * 2) + 2 * FST_B;    // 69632 + 104448 = 174080 B
    cudaFuncSetAttribute(flash_tc, cudaFuncAttributeMaxDynamicSharedMemorySize, (int)smem);
    flash_tc<<<dim3(H, B, S / 128), 256, smem>>>();

    // ---- output projection (fp16 single-term) ----
    gemm_out_h<<<dim3(D / 128, M / 128), 256, gsmh>>>(
        ah, woh, bo, out, M, D, H * HD);
}

// round 16
// speedup vs baseline: 1.1909x; 1.0465x over previous
#include <cuda_runtime.h>
#include <cuda_bf16.h>
#include <cuda_fp16.h>
#include <math.h>

#define B 4
#define S 2048
#define D 2048
#define H 16
#define G 4
#define HD 128
#define NQKV 3072   // packed q(2048) | k(512) | v(512)
#define NQK 2560    // q+k columns only

// ------------------------- scratch (device globals, no allocs) --------------
__device__ __nv_bfloat16 g_xh[(size_t)B * S * D];
__device__ __nv_bfloat16 g_xl[(size_t)B * S * D];
__device__ __half        g_xf[(size_t)B * S * D];          // x fp16 single (for V proj)
__device__ __nv_bfloat16 g_wqh[(size_t)D * NQKV];          // packed Wq|Wk hi [k][n]
__device__ __nv_bfloat16 g_wql[(size_t)D * NQKV];
__device__ __half        g_wvf[(size_t)D * 512];           // Wv fp16 [k][512]
__device__ __half        g_woh[(size_t)H * HD * D];        // Wo*32 (fp16 single)
__device__ __half        g_ah[(size_t)B * S * H * HD];     // attn out (fp16 single)
__device__ float         g_bqkv[NQKV];
__device__ float2        g_rope[(size_t)S * 64];           // (cos,sin) per (s, freq)
// pre-split, roped operands for flash
__device__ __nv_bfloat16 g_qsh[(size_t)B * H * S * HD];
__device__ __nv_bfloat16 g_qsl[(size_t)B * H * S * HD];
__device__ __nv_bfloat16 g_ksh[(size_t)B * G * S * HD];
__device__ __nv_bfloat16 g_ksl[(size_t)B * G * S * HD];
__device__ __half        g_vsh[(size_t)B * G * S * HD];

// ============================ shared PTX helpers =============================
#define LDSM4(R, addr)                                                        \
    asm volatile("ldmatrix.sync.aligned.m8n8.x4.shared.b16 {%0,%1,%2,%3}, [%4];" \
                 : "=r"(R[0]), "=r"(R[1]), "=r"(R[2]), "=r"(R[3]) : "r"(addr))
#define LDSM4T(R, addr)                                                       \
    asm volatile("ldmatrix.sync.aligned.m8n8.x4.trans.shared.b16 {%0,%1,%2,%3}, [%4];" \
                 : "=r"(R[0]), "=r"(R[1]), "=r"(R[2]), "=r"(R[3]) : "r"(addr))
#define MMA16816(d, a, b0v, b1v)                                              \
    asm volatile("mma.sync.aligned.m16n8k16.row.col.f32.bf16.bf16.f32 "       \
                 "{%0,%1,%2,%3},{%4,%5,%6,%7},{%8,%9},{%0,%1,%2,%3};"         \
                 : "+f"(d[0]), "+f"(d[1]), "+f"(d[2]), "+f"(d[3])             \
                 : "r"(a[0]), "r"(a[1]), "r"(a[2]), "r"(a[3]),                \
                   "r"(b0v), "r"(b1v))
#define MMA16816H(d, a, b0v, b1v)                                             \
    asm volatile("mma.sync.aligned.m16n8k16.row.col.f32.f16.f16.f32 "         \
                 "{%0,%1,%2,%3},{%4,%5,%6,%7},{%8,%9},{%0,%1,%2,%3};"         \
                 : "+f"(d[0]), "+f"(d[1]), "+f"(d[2]), "+f"(d[3])             \
                 : "r"(a[0]), "r"(a[1]), "r"(a[2]), "r"(a[3]),                \
                   "r"(b0v), "r"(b1v))
#define CP16(smaddr, gptr)                                                    \
    asm volatile("cp.async.cg.shared.global [%0], [%1], 16;" :: "r"(smaddr), "l"(gptr))
#define CP_COMMIT asm volatile("cp.async.commit_group;")

__device__ __forceinline__ void split2(float x, float y,
                                       unsigned& hi, unsigned& lo) {
    __nv_bfloat16 hx = __float2bfloat16_rn(x);
    __nv_bfloat16 hy = __float2bfloat16_rn(y);
    float rx = x - __bfloat162float(hx);
    float ry = y - __bfloat162float(hy);
    __nv_bfloat16 lx = __float2bfloat16_rn(rx);
    __nv_bfloat16 ly = __float2bfloat16_rn(ry);
    __nv_bfloat162 h2 = __nv_bfloat162(hx, hy);
    __nv_bfloat162 l2 = __nv_bfloat162(lx, ly);
    hi = *(unsigned*)&h2;
    lo = *(unsigned*)&l2;
}

__device__ __forceinline__ unsigned packh2(float x, float y) {
    __half2 h = __floats2half2_rn(x, y);
    return *(unsigned*)&h;
}

// ================= ONE fused conversion / packing / table kernel =============
#define CN0 4194304
#define CN1 1048576
#define CN2 262144
#define CN3 262144
#define CN4 1048576
#define CN5 3072
#define CN6 131072
#define CTOT (CN0 + CN1 + CN2 + CN3 + CN4 + CN5 + CN6)

__global__ void convert_all(const float* __restrict__ x,
                            const float* __restrict__ Wq,
                            const float* __restrict__ Wk,
                            const float* __restrict__ Wv,
                            const float* __restrict__ Wo,
                            const float* __restrict__ bq,
                            const float* __restrict__ bk,
                            const float* __restrict__ bv) {
    long i = (long)blockIdx.x * blockDim.x + threadIdx.x;
    if (i < CN0) {                  // x -> bf16 hi/lo + fp16 single
        float4 v = ((const float4*)x)[i];
        uint2 h, l;
        split2(v.x, v.y, h.x, l.x);
        split2(v.z, v.w, h.y, l.y);
        ((uint2*)g_xh)[i] = h;
        ((uint2*)g_xl)[i] = l;
        uint2 f;
        f.x = packh2(v.x, v.y);
        f.y = packh2(v.z, v.w);
        ((uint2*)g_xf)[i] = f;
    } else if (i < CN0 + CN1 + CN2) {   // Wq/Wk -> packed bf16 hi/lo
        long j;
        int srcN, off;
        const float* src;
        if (i < CN0 + CN1) { j = i - CN0;       srcN = 2048; off = 0;    src = Wq; }
        else               { j = i - CN0 - CN1; srcN = 512;  off = 2048; src = Wk; }
        int rw = srcN >> 2;
        int r = (int)(j / rw), c = (int)(j % rw) * 4;
        float4 v = *(const float4*)&src[(size_t)r * srcN + c];
        uint2 h, l;
        split2(v.x, v.y, h.x, l.x);
        split2(v.z, v.w, h.y, l.y);
        size_t d = (size_t)r * NQKV + off + c;
        *(uint2*)&g_wqh[d] = h;
        *(uint2*)&g_wql[d] = l;
    } else if (i < CN0 + CN1 + CN2 + CN3) {   // Wv -> fp16 [k][512]
        long j = i - CN0 - CN1 - CN2;
        float4 v = ((const float4*)Wv)[j];
        uint2 f;
        f.x = packh2(v.x, v.y);
        f.y = packh2(v.z, v.w);
        ((uint2*)g_wvf)[j] = f;
    } else if (i < CN0 + CN1 + CN2 + CN3 + CN4) {  // Wo*32 -> fp16
        long j = i - (CN0 + CN1 + CN2 + CN3);
        float4 v = ((const float4*)Wo)[j];
        uint2 h;
        h.x = packh2(v.x * 32.0f, v.y * 32.0f);
        h.y = packh2(v.z * 32.0f, v.w * 32.0f);
        ((uint2*)g_woh)[j] = h;
    } else if (i < CN0 + CN1 + CN2 + CN3 + CN4 + CN5) {
        int j = (int)(i - (CN0 + CN1 + CN2 + CN3 + CN4));
        g_bqkv[j] = (j < 2048) ? bq[j] : (j < 2560) ? bk[j - 2048] : bv[j - 2560];
    } else {
        int j = (int)(i - (CN0 + CN1 + CN2 + CN3 + CN4 + CN5));
        int s = j >> 6, f = j & 63;
        float inv_freq = powf(10000.0f, -(float)f / 64.0f);
        float ang = (float)s * inv_freq;
        g_rope[j] = make_float2(cosf(ang), sinf(ang));
    }
}

// ======================== bf16 3-term GEMM mainloop ==========================
#define LDA 40
#define LDB 136
#define ST_EL 18944   // per-stage smem elements: 2*128*40 + 2*32*136

struct GemmAcc { float a[4][4][4]; };

// 2-stage cp.async pipeline, term-major mma.
__device__ __forceinline__ void gemm_mainloop2(
    const __nv_bfloat16* __restrict__ Ahg, const __nv_bfloat16* __restrict__ Alg,
    const __nv_bfloat16* __restrict__ Bhg, const __nv_bfloat16* __restrict__ Blg,
    int K, int N, int row0, int col0, unsigned smBase, GemmAcc& acc) {
    const int tid = threadIdx.x;
    const int lane = tid & 31;
    const int warp = tid >> 5;
    const int wm = (warp >> 2) * 64;
    const int wn = (warp & 3) * 32;
    const int NT = K / 32;

    auto issue = [&](int st, int k0) {
        unsigned sb = smBase + st * (ST_EL * 2);
        #pragma unroll
        for (int j = 0; j < 2; j++) {
            int c = tid + j * 256;
            int r = c >> 2, c8 = (c & 3) * 8;
            unsigned so = (unsigned)(r * LDA + c8) * 2;
            CP16(sb + so, &Ahg[(size_t)(row0 + r) * K + k0 + c8]);
            CP16(sb + 10240 + so, &Alg[(size_t)(row0 + r) * K + k0 + c8]);
        }
        #pragma unroll
        for (int j = 0; j < 2; j++) {
            int c = tid + j * 256;
            int r = c >> 4, c8 = (c & 15) * 8;
            unsigned so = (unsigned)(r * LDB + c8) * 2;
            CP16(sb + 20480 + so, &Bhg[(size_t)(k0 + r) * N + col0 + c8]);
            CP16(sb + 29184 + so, &Blg[(size_t)(k0 + r) * N + col0 + c8]);
        }
    };

    issue(0, 0);
    CP_COMMIT;

    for (int it = 0; it < NT; it++) {
        if (it + 1 < NT) {
            issue((it + 1) & 1, (it + 1) * 32);
            CP_COMMIT;
            asm volatile("cp.async.wait_group 1;");
        } else {
            asm volatile("cp.async.wait_group 0;");
        }
        __syncthreads();

        unsigned sb = smBase + (it & 1) * (ST_EL * 2);
        const unsigned aBaseH = sb, aBaseL = sb + 10240;
        const unsigned bBaseH = sb + 20480, bBaseL = sb + 29184;

        #pragma unroll
        for (int ks = 0; ks < 2; ks++) {
            unsigned ah[4][4], al[4][4];
            #pragma unroll
            for (int im = 0; im < 4; im++) {
                unsigned off =
                    ((wm + im * 16 + (lane & 15)) * LDA + ks * 16 + (lane >> 4) * 8) * 2;
                LDSM4(ah[im], aBaseH + off);
                LDSM4(al[im], aBaseL + off);
            }
            int krow = ks * 16 + (lane & 7) + ((lane >> 3) & 1) * 8;
            #pragma unroll
            for (int pr = 0; pr < 2; pr++) {
                unsigned bh[4], bl[4];
                unsigned off = (krow * LDB + wn + pr * 16 + (lane >> 4) * 8) * 2;
                LDSM4T(bh, bBaseH + off);
                LDSM4T(bl, bBaseL + off);
                #pragma unroll
                for (int im = 0; im < 4; im++)
                    MMA16816(acc.a[im][pr * 2 + 0], ah[im], bh[0], bh[1]);
                #pragma unroll
                for (int im = 0; im < 4; im++)
                    MMA16816(acc.a[im][pr * 2 + 1], ah[im], bh[2], bh[3]);
                #pragma unroll
                for (int im = 0; im < 4; im++)
                    MMA16816(acc.a[im][pr * 2 + 0], ah[im], bl[0], bl[1]);
                #pragma unroll
                for (int im = 0; im < 4; im++)
                    MMA16816(acc.a[im][pr * 2 + 1], ah[im], bl[2], bl[3]);
                #pragma unroll
                for (int im = 0; im < 4; im++)
                    MMA16816(acc.a[im][pr * 2 + 0], al[im], bh[0], bh[1]);
                #pragma unroll
                for (int im = 0; im < 4; im++)
                    MMA16816(acc.a[im][pr * 2 + 1], al[im], bh[2], bh[3]);
            }
        }
        __syncthreads();
    }
}

// ====== QK projection GEMM (cols 0..2559) + fused bias/RoPE/split epilogue ===
#define STF 132

__global__ __launch_bounds__(256, 2) void gemm_qk_fused(
    const __nv_bfloat16* __restrict__ Ahg, const __nv_bfloat16* __restrict__ Alg,
    const __nv_bfloat16* __restrict__ Bhg, const __nv_bfloat16* __restrict__ Blg,
    const float* __restrict__ bias) {
    extern __shared__ __nv_bfloat16 smem[];
    const unsigned smBase = (unsigned)__cvta_generic_to_shared(smem);

    const int tid = threadIdx.x;
    const int lane = tid & 31;
    const int warp = tid >> 5;
    const int wm = (warp >> 2) * 64;
    const int wn = (warp & 3) * 32;
    const int row0 = blockIdx.y * 128;
    const int col0 = blockIdx.x * 128;   // 0..2432 (20 tiles)

    GemmAcc acc = {};
    gemm_mainloop2(Ahg, Alg, Bhg, Blg, D, NQKV, row0, col0, smBase, acc);

    float* st = (float*)smem;
    const int qr = lane >> 2, qc = lane & 3;
    #pragma unroll
    for (int im = 0; im < 4; im++) {
        #pragma unroll
        for (int jn = 0; jn < 4; jn++) {
            int rr = wm + im * 16 + qr;
            int cc = wn + jn * 8 + 2 * qc;
            float b0v = bias[col0 + cc], b1v = bias[col0 + cc + 1];
            st[rr * STF + cc]           = acc.a[im][jn][0] + b0v;
            st[rr * STF + cc + 1]       = acc.a[im][jn][1] + b1v;
            st[(rr + 8) * STF + cc]     = acc.a[im][jn][2] + b0v;
            st[(rr + 8) * STF + cc + 1] = acc.a[im][jn][3] + b1v;
        }
    }
    __syncthreads();

    const int tile = col0 >> 7;      // 0-15 q, 16-19 k
    const int bb = row0 >> 11;
    const float scale = 0.08838834764831845f;

    bool isq = tile < 16;
    int hh = isq ? tile : tile - 16;
    int nh = isq ? H : G;
    __nv_bfloat16* dh = isq ? g_qsh : g_ksh;
    __nv_bfloat16* dl = isq ? g_qsl : g_ksl;
    float sc = isq ? scale : 1.0f;
    #pragma unroll 4
    for (int t = 0; t < 16; t++) {
        int idx = tid + t * 256;
        int r = idx >> 5;
        int i2 = (idx & 31) * 2;
        int s = (row0 + r) & (S - 1);
        float a0 = st[r * STF + i2],      a1 = st[r * STF + i2 + 1];
        float c0 = st[r * STF + i2 + 64], c1 = st[r * STF + i2 + 65];
        float4 tcs = *(const float4*)&g_rope[(size_t)s * 64 + i2];
        float o10 = (a0 * tcs.x - c0 * tcs.y) * sc;
        float o11 = (a1 * tcs.z - c1 * tcs.w) * sc;
        float o20 = (c0 * tcs.x + a0 * tcs.y) * sc;
        float o21 = (c1 * tcs.z + a1 * tcs.w) * sc;
        unsigned h1, l1, h2, l2;
        split2(o10, o11, h1, l1);
        split2(o20, o21, h2, l2);
        size_t dst = ((size_t)(bb * nh + hh) * S + s) * HD + i2;
        *(unsigned*)&dh[dst] = h1;
        *(unsigned*)&dl[dst] = l1;
        *(unsigned*)&dh[dst + 64] = h2;
        *(unsigned*)&dl[dst + 64] = l2;
    }
}

// ============== shared fp16 single-term mainloop (3-stage) ===================
#define STH_EL 9472   // per-stage elements: 128*40 + 32*136

__device__ __forceinline__ void gemm_h_mainloop(
    const __half* __restrict__ Ag, const __half* __restrict__ Bg,
    int K, int N, int row0, int col0, unsigned smBase, float (*acc)[4][4]) {
    const int tid = threadIdx.x;
    const int lane = tid & 31;
    const int warp = tid >> 5;
    const int wm = (warp >> 2) * 64;
    const int wn = (warp & 3) * 32;
    const int NT = K / 32;

    auto issue = [&](int st, int k0) {
        unsigned sb = smBase + st * (STH_EL * 2);
        #pragma unroll
        for (int j = 0; j < 2; j++) {
            int c = tid + j * 256;
            int r = c >> 2, c8 = (c & 3) * 8;
            unsigned so = (unsigned)(r * LDA + c8) * 2;
            CP16(sb + so, &Ag[(size_t)(row0 + r) * K + k0 + c8]);
        }
        #pragma unroll
        for (int j = 0; j < 2; j++) {
            int c = tid + j * 256;
            int r = c >> 4, c8 = (c & 15) * 8;
            unsigned so = (unsigned)(r * LDB + c8) * 2;
            CP16(sb + 10240 + so, &Bg[(size_t)(k0 + r) * N + col0 + c8]);
        }
    };

    issue(0, 0);
    CP_COMMIT;
    issue(1, 32);
    CP_COMMIT;

    for (int it = 0; it < NT; it++) {
        if (it == NT - 1) {
            asm volatile("cp.async.wait_group 0;");
        } else {
            asm volatile("cp.async.wait_group 1;");
        }
        __syncthreads();
        if (it + 2 < NT) {
            issue((it + 2) % 3, (it + 2) * 32);
            CP_COMMIT;
        }

        unsigned sb = smBase + (it % 3) * (STH_EL * 2);
        const unsigned aBase = sb;
        const unsigned bBase = sb + 10240;

        #pragma unroll
        for (int ks = 0; ks < 2; ks++) {
            unsigned ah[4][4];
            #pragma unroll
            for (int im = 0; im < 4; im++) {
                unsigned off =
                    ((wm + im * 16 + (lane & 15)) * LDA + ks * 16 + (lane >> 4) * 8) * 2;
                LDSM4(ah[im], aBase + off);
            }
            int krow = ks * 16 + (lane & 7) + ((lane >> 3) & 1) * 8;
            #pragma unroll
            for (int pr = 0; pr < 2; pr++) {
                unsigned bh[4];
                unsigned off = (krow * LDB + wn + pr * 16 + (lane >> 4) * 8) * 2;
                LDSM4T(bh, bBase + off);
                #pragma unroll
                for (int im = 0; im < 4; im++) {
                    MMA16816H(acc[im][pr * 2 + 0], ah[im], bh[0], bh[1]);
                    MMA16816H(acc[im][pr * 2 + 1], ah[im], bh[2], bh[3]);
                }
            }
        }
    }
}

// ============ output projection: A fp16 single x W fp16 single ===============
__global__ __launch_bounds__(256) void gemm_out_h(
    const __half* __restrict__ Ag, const __half* __restrict__ Bg,
    const float* __restrict__ bias, float* __restrict__ C,
    int M, int N, int K) {
    extern __shared__ __nv_bfloat16 smemb[];
    const unsigned smBase = (unsigned)__cvta_generic_to_shared(smemb);

    const int tid = threadIdx.x;
    const int lane = tid & 31;
    const int warp = tid >> 5;
    const int wm = (warp >> 2) * 64;
    const int wn = (warp & 3) * 32;
    const int row0 = blockIdx.y * 128;
    const int col0 = blockIdx.x * 128;

    float acc[4][4][4] = {};
    gemm_h_mainloop(Ag, Bg, K, N, row0, col0, smBase, acc);

    const float inv32 = 1.0f / 32.0f;
    const int qr = lane >> 2, qc = lane & 3;
    #pragma unroll
    for (int im = 0; im < 4; im++) {
        #pragma unroll
        for (int jn = 0; jn < 4; jn++) {
            int row = row0 + wm + im * 16 + qr;
            int col = col0 + wn + jn * 8 + 2 * qc;
            float b0v = bias[col], b1v = bias[col + 1];
            float2 o0 = make_float2(acc[im][jn][0] * inv32 + b0v,
                                    acc[im][jn][1] * inv32 + b1v);
            float2 o1 = make_float2(acc[im][jn][2] * inv32 + b0v,
                                    acc[im][jn][3] * inv32 + b1v);
            *(float2*)&C[(size_t)row * N + col] = o0;
            *(float2*)&C[(size_t)(row + 8) * N + col] = o1;
        }
    }
}

// ======= V projection: x fp16 @ Wv fp16 (1-term), writes g_vsh directly ======
__global__ __launch_bounds__(256) void gemm_v_h(
    const __half* __restrict__ Ag, const __half* __restrict__ Bg,
    const float* __restrict__ bv) {
    extern __shared__ __nv_bfloat16 smemb[];
    const unsigned smBase = (unsigned)__cvta_generic_to_shared(smemb);

    const int tid = threadIdx.x;
    const int lane = tid & 31;
    const int warp = tid >> 5;
    const int wm = (warp >> 2) * 64;
    const int wn = (warp & 3) * 32;
    const int row0 = blockIdx.y * 128;
    const int col0 = blockIdx.x * 128;   // 0..384

    float acc[4][4][4] = {};
    gemm_h_mainloop(Ag, Bg, D, 512, row0, col0, smBase, acc);

    const int gg = col0 >> 7;
    const int qr = lane >> 2, qc = lane & 3;
    #pragma unroll
    for (int im = 0; im < 4; im++) {
        #pragma unroll
        for (int jn = 0; jn < 4; jn++) {
            int row = row0 + wm + im * 16 + qr;
            int hd = wn + jn * 8 + 2 * qc;        // 0..126
            float b0v = bv[col0 + hd], b1v = bv[col0 + hd + 1];
            int s0 = row & (S - 1), bb = row >> 11;
            size_t d0 = ((size_t)(bb * G + gg) * S + s0) * HD + hd;
            *(unsigned*)&g_vsh[d0] = packh2(acc[im][jn][0] + b0v, acc[im][jn][1] + b1v);
            int row1 = row + 8;
            int s1 = row1 & (S - 1), bb1 = row1 >> 11;
            size_t d1 = ((size_t)(bb1 * G + gg) * S + s1) * HD + hd;
            *(unsigned*)&g_vsh[d1] = packh2(acc[im][jn][2] + b0v, acc[im][jn][3] + b1v);
        }
    }
}

// == Flash attention: 128-row q tiles, cp.async double-buffered K/V tiles =====
#define LQ 136
#define FST_B (3 * 64 * LQ * 2)   // bytes per K/V stage (Kh,Kl,Vh)

__global__ __launch_bounds__(256) void flash_tc() {
    extern __shared__ __nv_bfloat16 smb[];
    __nv_bfloat16* Qh = smb;
    __nv_bfloat16* Ql = Qh + 128 * LQ;
    const unsigned smBase = (unsigned)__cvta_generic_to_shared(smb);
    const unsigned kvBase = smBase + 2 * 128 * LQ * 2;

    const int tid  = threadIdx.x;
    const int lane = tid & 31;
    const int warp = tid >> 5;
    const int qtile = gridDim.z - 1 - blockIdx.z;
    const int h  = blockIdx.x;
    const int b  = blockIdx.y;
    const int g  = h / (H / G);
    const int q0 = qtile * 128;
    const int wm = warp * 16;

    const unsigned qBH = smBase;
    const unsigned qBL = smBase + 128 * LQ * 2;

    auto kv_issue = [&](int st, int kt2) {
        int k0 = kt2 * 64;
        unsigned sb = kvBase + st * FST_B;
        #pragma unroll
        for (int it = 0; it < 4; it++) {
            int i4 = tid + it * 256;
            int r  = i4 >> 4;
            int c8 = (i4 & 15) * 8;
            size_t gi = ((size_t)(b * G + g) * S + k0 + r) * HD + c8;
            unsigned so = (unsigned)(r * LQ + c8) * 2;
            CP16(sb + so, g_ksh + gi);
            CP16(sb + 64 * LQ * 2 + so, g_ksl + gi);
            CP16(sb + 128 * LQ * 2 + so, g_vsh + gi);
        }
    };

    kv_issue(0, 0);
    CP_COMMIT;

    #pragma unroll
    for (int it = 0; it < 8; it++) {
        int i4 = tid + it * 256;
        int r  = i4 >> 4;
        int c8 = (i4 & 15) * 8;
        size_t gi = ((size_t)(b * H + h) * S + q0 + r) * HD + c8;
        *(uint4*)&Qh[r * LQ + c8] = *(const uint4*)&g_qsh[gi];
        *(uint4*)&Ql[r * LQ + c8] = *(const uint4*)&g_qsl[gi];
    }

    const int gid = lane >> 2, tig = lane & 3;
    const int row0g = q0 + wm + gid;
    const int row1g = row0g + 8;
    const int wmaxrow = q0 + wm + 15;

    float rm0 = -1e30f, rm1 = -1e30f, rl0 = 0.0f, rl1 = 0.0f;
    float oacc[16][4] = {};

    const int NKT = 2 * qtile + 2;
    for (int kt = 0; kt < NKT; kt++) {
        const int k0 = kt * 64;
        if (kt + 1 < NKT) {
            kv_issue((kt + 1) & 1, kt + 1);
            CP_COMMIT;
            asm volatile("cp.async.wait_group 1;");
        } else {
            asm volatile("cp.async.wait_group 0;");
        }
        __syncthreads();

        unsigned sb = kvBase + (kt & 1) * FST_B;
        const unsigned kBH = sb;
        const unsigned kBL = sb + 64 * LQ * 2;
        const unsigned vBH = sb + 128 * LQ * 2;

        if (k0 <= wmaxrow) {
            float sacc[8][4] = {};
            #pragma unroll
            for (int ks = 0; ks < 8; ks++) {
                unsigned ah[4], al[4];
                unsigned offa = ((wm + (lane & 15)) * LQ + ks * 16 + (lane >> 4) * 8) * 2;
                LDSM4(ah, qBH + offa);
                LDSM4(al, qBL + offa);
                #pragma unroll
                for (int np = 0; np < 2; np++) {
                    unsigned kh0[4], kl0[4], kh1[4], kl1[4];
                    unsigned ob0 = (((2 * np + 0) * 16 + (lane >> 4) * 8 + (lane & 7)) * LQ +
                                    ks * 16 + ((lane >> 3) & 1) * 8) * 2;
                    unsigned ob1 = (((2 * np + 1) * 16 + (lane >> 4) * 8 + (lane & 7)) * LQ +
                                    ks * 16 + ((lane >> 3) & 1) * 8) * 2;
                    LDSM4(kh0, kBH + ob0);
                    LDSM4(kl0, kBL + ob0);
                    LDSM4(kh1, kBH + ob1);
                    LDSM4(kl1, kBL + ob1);
                    MMA16816(sacc[4 * np + 0], ah, kh0[0], kh0[1]);
                    MMA16816(sacc[4 * np + 1], ah, kh0[2], kh0[3]);
                    MMA16816(sacc[4 * np + 2], ah, kh1[0], kh1[1]);
                    MMA16816(sacc[4 * np + 3], ah, kh1[2], kh1[3]);
                    MMA16816(sacc[4 * np + 0], ah, kl0[0], kl0[1]);
                    MMA16816(sacc[4 * np + 1], ah, kl0[2], kl0[3]);
                    MMA16816(sacc[4 * np + 2], ah, kl1[0], kl1[1]);
                    MMA16816(sacc[4 * np + 3], ah, kl1[2], kl1[3]);
                    MMA16816(sacc[4 * np + 0], al, kh0[0], kh0[1]);
                    MMA16816(sacc[4 * np + 1], al, kh0[2], kh0[3]);
                    MMA16816(sacc[4 * np + 2], al, kh1[0], kh1[1]);
                    MMA16816(sacc[4 * np + 3], al, kh1[2], kh1[3]);
                }
            }

            if (k0 + 63 > row0g) {
                #pragma unroll
                for (int nt = 0; nt < 8; nt++) {
                    int colg = k0 + nt * 8 + 2 * tig;
                    if (colg > row0g)     sacc[nt][0] = -1e30f;
                    if (colg + 1 > row0g) sacc[nt][1] = -1e30f;
                    if (colg > row1g)     sacc[nt][2] = -1e30f;
                    if (colg + 1 > row1g) sacc[nt][3] = -1e30f;
                }
            }

            float mx0 = rm0, mx1 = rm1;
            #pragma unroll
            for (int nt = 0; nt < 8; nt++) {
                mx0 = fmaxf(mx0, fmaxf(sacc[nt][0], sacc[nt][1]));
                mx1 = fmaxf(mx1, fmaxf(sacc[nt][2], sacc[nt][3]));
            }
            mx0 = fmaxf(mx0, __shfl_xor_sync(0xffffffff, mx0, 1));
            mx0 = fmaxf(mx0, __shfl_xor_sync(0xffffffff, mx0, 2));
            mx1 = fmaxf(mx1, __shfl_xor_sync(0xffffffff, mx1, 1));
            mx1 = fmaxf(mx1, __shfl_xor_sync(0xffffffff, mx1, 2));
            float sc0 = __expf(rm0 - mx0);
            float sc1 = __expf(rm1 - mx1);
            rm0 = mx0; rm1 = mx1;
            float sum0 = 0.0f, sum1 = 0.0f;
            #pragma unroll
            for (int nt = 0; nt < 8; nt++) {
                sacc[nt][0] = __expf(sacc[nt][0] - mx0);
                sacc[nt][1] = __expf(sacc[nt][1] - mx0);
                sacc[nt][2] = __expf(sacc[nt][2] - mx1);
                sacc[nt][3] = __expf(sacc[nt][3] - mx1);
                sum0 += sacc[nt][0] + sacc[nt][1];
                sum1 += sacc[nt][2] + sacc[nt][3];
            }
            sum0 += __shfl_xor_sync(0xffffffff, sum0, 1);
            sum0 += __shfl_xor_sync(0xffffffff, sum0, 2);
            sum1 += __shfl_xor_sync(0xffffffff, sum1, 1);
            sum1 += __shfl_xor_sync(0xffffffff, sum1, 2);
            rl0 = rl0 * sc0 + sum0;
            rl1 = rl1 * sc1 + sum1;
            #pragma unroll
            for (int nt = 0; nt < 16; nt++) {
                oacc[nt][0] *= sc0; oacc[nt][1] *= sc0;
                oacc[nt][2] *= sc1; oacc[nt][3] *= sc1;
            }

            #pragma unroll
            for (int j = 0; j < 4; j++) {
                unsigned ph[4];
                ph[0] = packh2(sacc[2 * j][0],     sacc[2 * j][1]);
                ph[1] = packh2(sacc[2 * j][2],     sacc[2 * j][3]);
                ph[2] = packh2(sacc[2 * j + 1][0], sacc[2 * j + 1][1]);
                ph[3] = packh2(sacc[2 * j + 1][2], sacc[2 * j + 1][3]);
                #pragma unroll
                for (int nb = 0; nb < 8; nb++) {
                    unsigned vh4[4];
                    unsigned offv = ((j * 16 + (lane & 7) + ((lane >> 3) & 1) * 8) * LQ +
                                     nb * 16 + (lane >> 4) * 8) * 2;
                    LDSM4T(vh4, vBH + offv);
                    MMA16816H(oacc[2 * nb + 0], ph, vh4[0], vh4[1]);
                    MMA16816H(oacc[2 * nb + 1], ph, vh4[2], vh4[3]);
                }
            }
        }
        __syncthreads();
    }

    float li0 = 1.0f / rl0, li1 = 1.0f / rl1;
    size_t or0 = (size_t)(b * S + row0g) * (H * HD) + h * HD;
    size_t or1 = (size_t)(b * S + row1g) * (H * HD) + h * HD;
    #pragma unroll
    for (int nt = 0; nt < 16; nt++) {
        int col = nt * 8 + 2 * tig;
        *(unsigned*)&g_ah[or0 + col] = packh2(oacc[nt][0] * li0, oacc[nt][1] * li0);
        *(unsigned*)&g_ah[or1 + col] = packh2(oacc[nt][2] * li1, oacc[nt][3] * li1);
    }
}

// =============================== launch ======================================
extern "C" void kernel_launch(void* const* d_in, const int* in_sizes, int n_in,
                              void* d_out, int out_size) {
    const float* x  = (const float*)d_in[0];
    const float* Wq = (const float*)d_in[1];
    const float* bq = (const float*)d_in[2];
    const float* Wk = (const float*)d_in[3];
    const float* bk = (const float*)d_in[4];
    const float* Wv = (const float*)d_in[5];
    const float* bv = (const float*)d_in[6];
    const float* Wo = (const float*)d_in[7];
    const float* bo = (const float*)d_in[8];
    float* out = (float*)d_out;

    __nv_bfloat16 *xh, *xl, *wqh, *wql;
    __half *xf, *wvf, *woh, *ah;
    float *bqkv;
    cudaGetSymbolAddress((void**)&xh, g_xh);
    cudaGetSymbolAddress((void**)&xl, g_xl);
    cudaGetSymbolAddress((void**)&xf, g_xf);
    cudaGetSymbolAddress((void**)&wqh, g_wqh);
    cudaGetSymbolAddress((void**)&wql, g_wql);
    cudaGetSymbolAddress((void**)&wvf, g_wvf);
    cudaGetSymbolAddress((void**)&woh, g_woh);
    cudaGetSymbolAddress((void**)&ah, g_ah);
    cudaGetSymbolAddress((void**)&bqkv, g_bqkv);

    const int M = B * S;  // 8192

    convert_all<<<(CTOT + 255) / 256, 256>>>(x, Wq, Wk, Wv, Wo, bq, bk, bv);

    size_t gsm = (size_t)2 * ST_EL * sizeof(__nv_bfloat16);  // 75776 B
    cudaFuncSetAttribute(gemm_qk_fused, cudaFuncAttributeMaxDynamicSharedMemorySize, (int)gsm);
    size_t gsmh = (size_t)3 * STH_EL * sizeof(__half);       // 56832 B
    cudaFuncSetAttribute(gemm_out_h, cudaFuncAttributeMaxDynamicSharedMemorySize, (int)gsmh);
    cudaFuncSetAttribute(gemm_v_h, cudaFuncAttributeMaxDynamicSharedMemorySize, (int)gsmh);

    // ---- QK projection (3-term bf16, rope/split fused) ----
    gemm_qk_fused<<<dim3(NQK / 128, M / 128), 256, gsm>>>(xh, xl, wqh, wql, bqkv);

    // ---- V projection (1-term fp16, writes g_vsh) ----
    gemm_v_h<<<dim3(512 / 128, M / 128), 256, gsmh>>>(xf, wvf, bv);

    // ---- flash attention (double-buffered K/V) ----
    size_t smem = (size_t)(2 * 128 * LQ * 2) + 2 * FST_B;    // 174080 B
    cudaFuncSetAttribute(flash_tc, cudaFuncAttributeMaxDynamicSharedMemorySize, (int)smem);
    flash_tc<<<dim3(H, B, S / 128), 256, smem>>>();

    // ---- output projection (fp16 single-term) ----
    gemm_out_h<<<dim3(D / 128, M / 128), 256, gsmh>>>(
        ah, woh, bo, out, M, D, H * HD);
}

// round 17
// speedup vs baseline: 1.4113x; 1.1851x over previous
#include <cuda_runtime.h>
#include <cuda_bf16.h>
#include <cuda_fp16.h>
#include <math.h>

#define B 4
#define S 2048
#define D 2048
#define H 16
#define G 4
#define HD 128
#define NQKV 3072
#define NQK 2560    // q+k columns only

// ------------------------- scratch (device globals, no allocs) --------------
__device__ __half        g_xf[(size_t)B * S * D];          // x fp16 single
__device__ __half        g_wqkh[(size_t)D * NQK];          // Wq|Wk *32 fp16 hi [k][n]
__device__ __half        g_wqkl[(size_t)D * NQK];          // Wq|Wk *32 fp16 lo
__device__ __half        g_wvf[(size_t)D * 512];           // Wv fp16 [k][512]
__device__ __half        g_woh[(size_t)H * HD * D];        // Wo*32 (fp16 single)
__device__ __half        g_ah[(size_t)B * S * H * HD];     // attn out (fp16 single)
__device__ float         g_bqkv[NQKV];
__device__ float2        g_rope[(size_t)S * 64];           // (cos,sin) per (s, freq)
// pre-split, roped operands for flash
__device__ __nv_bfloat16 g_qsh[(size_t)B * H * S * HD];
__device__ __nv_bfloat16 g_qsl[(size_t)B * H * S * HD];
__device__ __nv_bfloat16 g_ksh[(size_t)B * G * S * HD];
__device__ __nv_bfloat16 g_ksl[(size_t)B * G * S * HD];
__device__ __half        g_vsh[(size_t)B * G * S * HD];

// ============================ shared PTX helpers =============================
#define LDSM4(R, addr)                                                        \
    asm volatile("ldmatrix.sync.aligned.m8n8.x4.shared.b16 {%0,%1,%2,%3}, [%4];" \
                 : "=r"(R[0]), "=r"(R[1]), "=r"(R[2]), "=r"(R[3]) : "r"(addr))
#define LDSM4T(R, addr)                                                       \
    asm volatile("ldmatrix.sync.aligned.m8n8.x4.trans.shared.b16 {%0,%1,%2,%3}, [%4];" \
                 : "=r"(R[0]), "=r"(R[1]), "=r"(R[2]), "=r"(R[3]) : "r"(addr))
#define MMA16816(d, a, b0v, b1v)                                              \
    asm volatile("mma.sync.aligned.m16n8k16.row.col.f32.bf16.bf16.f32 "       \
                 "{%0,%1,%2,%3},{%4,%5,%6,%7},{%8,%9},{%0,%1,%2,%3};"         \
                 : "+f"(d[0]), "+f"(d[1]), "+f"(d[2]), "+f"(d[3])             \
                 : "r"(a[0]), "r"(a[1]), "r"(a[2]), "r"(a[3]),                \
                   "r"(b0v), "r"(b1v))
#define MMA16816H(d, a, b0v, b1v)                                             \
    asm volatile("mma.sync.aligned.m16n8k16.row.col.f32.f16.f16.f32 "         \
                 "{%0,%1,%2,%3},{%4,%5,%6,%7},{%8,%9},{%0,%1,%2,%3};"         \
                 : "+f"(d[0]), "+f"(d[1]), "+f"(d[2]), "+f"(d[3])             \
                 : "r"(a[0]), "r"(a[1]), "r"(a[2]), "r"(a[3]),                \
                   "r"(b0v), "r"(b1v))
#define CP16(smaddr, gptr)                                                    \
    asm volatile("cp.async.cg.shared.global [%0], [%1], 16;" :: "r"(smaddr), "l"(gptr))
#define CP_COMMIT asm volatile("cp.async.commit_group;")

__device__ __forceinline__ void split2(float x, float y,
                                       unsigned& hi, unsigned& lo) {
    __nv_bfloat16 hx = __float2bfloat16_rn(x);
    __nv_bfloat16 hy = __float2bfloat16_rn(y);
    float rx = x - __bfloat162float(hx);
    float ry = y - __bfloat162float(hy);
    __nv_bfloat16 lx = __float2bfloat16_rn(rx);
    __nv_bfloat16 ly = __float2bfloat16_rn(ry);
    __nv_bfloat162 h2 = __nv_bfloat162(hx, hy);
    __nv_bfloat162 l2 = __nv_bfloat162(lx, ly);
    hi = *(unsigned*)&h2;
    lo = *(unsigned*)&l2;
}

__device__ __forceinline__ void split2h(float x, float y,
                                        unsigned& hi, unsigned& lo) {
    __half hx = __float2half_rn(x);
    __half hy = __float2half_rn(y);
    float rx = x - __half2float(hx);
    float ry = y - __half2float(hy);
    __half2 h2 = __halves2half2(hx, hy);
    __half2 l2 = __halves2half2(__float2half_rn(rx), __float2half_rn(ry));
    hi = *(unsigned*)&h2;
    lo = *(unsigned*)&l2;
}

__device__ __forceinline__ unsigned packh2(float x, float y) {
    __half2 h = __floats2half2_rn(x, y);
    return *(unsigned*)&h;
}

// ================= ONE fused conversion / packing / table kernel =============
#define CN0 4194304                 // x quads
#define CN1 1048576                 // Wq quads
#define CN2 262144                  // Wk quads
#define CN3 262144                  // Wv quads
#define CN4 1048576                 // Wo quads
#define CN5 3072                    // bias
#define CN6 131072                  // rope table
#define CTOT (CN0 + CN1 + CN2 + CN3 + CN4 + CN5 + CN6)

__global__ void convert_all(const float* __restrict__ x,
                            const float* __restrict__ Wq,
                            const float* __restrict__ Wk,
                            const float* __restrict__ Wv,
                            const float* __restrict__ Wo,
                            const float* __restrict__ bq,
                            const float* __restrict__ bk,
                            const float* __restrict__ bv) {
    long i = (long)blockIdx.x * blockDim.x + threadIdx.x;
    if (i < CN0) {                  // x -> fp16 single
        float4 v = ((const float4*)x)[i];
        uint2 f;
        f.x = packh2(v.x, v.y);
        f.y = packh2(v.z, v.w);
        ((uint2*)g_xf)[i] = f;
    } else if (i < CN0 + CN1 + CN2) {   // Wq/Wk *32 -> fp16 hi/lo [k][NQK]
        long j;
        int srcN, off;
        const float* src;
        if (i < CN0 + CN1) { j = i - CN0;       srcN = 2048; off = 0;    src = Wq; }
        else               { j = i - CN0 - CN1; srcN = 512;  off = 2048; src = Wk; }
        int rw = srcN >> 2;
        int r = (int)(j / rw), c = (int)(j % rw) * 4;
        float4 v = *(const float4*)&src[(size_t)r * srcN + c];
        uint2 h, l;
        split2h(v.x * 32.0f, v.y * 32.0f, h.x, l.x);
        split2h(v.z * 32.0f, v.w * 32.0f, h.y, l.y);
        size_t d = (size_t)r * NQK + off + c;
        *(uint2*)&g_wqkh[d] = h;
        *(uint2*)&g_wqkl[d] = l;
    } else if (i < CN0 + CN1 + CN2 + CN3) {   // Wv -> fp16 [k][512]
        long j = i - CN0 - CN1 - CN2;
        float4 v = ((const float4*)Wv)[j];
        uint2 f;
        f.x = packh2(v.x, v.y);
        f.y = packh2(v.z, v.w);
        ((uint2*)g_wvf)[j] = f;
    } else if (i < CN0 + CN1 + CN2 + CN3 + CN4) {  // Wo*32 -> fp16
        long j = i - (CN0 + CN1 + CN2 + CN3);
        float4 v = ((const float4*)Wo)[j];
        uint2 h;
        h.x = packh2(v.x * 32.0f, v.y * 32.0f);
        h.y = packh2(v.z * 32.0f, v.w * 32.0f);
        ((uint2*)g_woh)[j] = h;
    } else if (i < CN0 + CN1 + CN2 + CN3 + CN4 + CN5) {
        int j = (int)(i - (CN0 + CN1 + CN2 + CN3 + CN4));
        g_bqkv[j] = (j < 2048) ? bq[j] : (j < 2560) ? bk[j - 2048] : bv[j - 2560];
    } else {
        int j = (int)(i - (CN0 + CN1 + CN2 + CN3 + CN4 + CN5));
        int s = j >> 6, f = j & 63;
        float inv_freq = powf(10000.0f, -(float)f / 64.0f);
        float ang = (float)s * inv_freq;
        g_rope[j] = make_float2(cosf(ang), sinf(ang));
    }
}

// ============================= GEMM constants ================================
#define LDA 40
#define LDB 136
#define STF 132       // fp32 smem stride for QK epilogue tile

// ====== QK projection: x fp16 single x Wqk fp16 hi/lo (2-term), 3-stage ======
#define QK_ST_B 27648   // stage bytes: A 10240 + Bh 8704 + Bl 8704

__global__ __launch_bounds__(256, 2) void gemm_qk_fused(
    const __half* __restrict__ Ag,
    const __half* __restrict__ Bhg, const __half* __restrict__ Blg,
    const float* __restrict__ bias) {
    extern __shared__ __nv_bfloat16 smemb[];
    const unsigned smBase = (unsigned)__cvta_generic_to_shared(smemb);

    const int tid = threadIdx.x;
    const int lane = tid & 31;
    const int warp = tid >> 5;
    const int wm = (warp >> 2) * 64;
    const int wn = (warp & 3) * 32;
    const int row0 = blockIdx.y * 128;
    const int col0 = blockIdx.x * 128;   // 0..2432
    const int NT = D / 32;

    float acc[4][4][4] = {};

    auto issue = [&](int st, int k0) {
        unsigned sb = smBase + st * QK_ST_B;
        #pragma unroll
        for (int j = 0; j < 2; j++) {
            int c = tid + j * 256;
            int r = c >> 2, c8 = (c & 3) * 8;
            unsigned so = (unsigned)(r * LDA + c8) * 2;
            CP16(sb + so, &Ag[(size_t)(row0 + r) * D + k0 + c8]);
        }
        #pragma unroll
        for (int j = 0; j < 2; j++) {
            int c = tid + j * 256;
            int r = c >> 4, c8 = (c & 15) * 8;
            unsigned so = (unsigned)(r * LDB + c8) * 2;
            CP16(sb + 10240 + so, &Bhg[(size_t)(k0 + r) * NQK + col0 + c8]);
            CP16(sb + 18944 + so, &Blg[(size_t)(k0 + r) * NQK + col0 + c8]);
        }
    };

    issue(0, 0);
    CP_COMMIT;
    issue(1, 32);
    CP_COMMIT;

    for (int it = 0; it < NT; it++) {
        if (it == NT - 1) {
            asm volatile("cp.async.wait_group 0;");
        } else {
            asm volatile("cp.async.wait_group 1;");
        }
        __syncthreads();
        if (it + 2 < NT) {
            issue((it + 2) % 3, (it + 2) * 32);
            CP_COMMIT;
        }

        unsigned sb = smBase + (it % 3) * QK_ST_B;
        const unsigned aBase = sb;
        const unsigned bBaseH = sb + 10240, bBaseL = sb + 18944;

        #pragma unroll
        for (int ks = 0; ks < 2; ks++) {
            unsigned ah[4][4];
            #pragma unroll
            for (int im = 0; im < 4; im++) {
                unsigned off =
                    ((wm + im * 16 + (lane & 15)) * LDA + ks * 16 + (lane >> 4) * 8) * 2;
                LDSM4(ah[im], aBase + off);
            }
            int krow = ks * 16 + (lane & 7) + ((lane >> 3) & 1) * 8;
            #pragma unroll
            for (int pr = 0; pr < 2; pr++) {
                unsigned bh[4], bl[4];
                unsigned off = (krow * LDB + wn + pr * 16 + (lane >> 4) * 8) * 2;
                LDSM4T(bh, bBaseH + off);
                LDSM4T(bl, bBaseL + off);
                #pragma unroll
                for (int im = 0; im < 4; im++)
                    MMA16816H(acc[im][pr * 2 + 0], ah[im], bh[0], bh[1]);
                #pragma unroll
                for (int im = 0; im < 4; im++)
                    MMA16816H(acc[im][pr * 2 + 1], ah[im], bh[2], bh[3]);
                #pragma unroll
                for (int im = 0; im < 4; im++)
                    MMA16816H(acc[im][pr * 2 + 0], ah[im], bl[0], bl[1]);
                #pragma unroll
                for (int im = 0; im < 4; im++)
                    MMA16816H(acc[im][pr * 2 + 1], ah[im], bl[2], bl[3]);
            }
        }
    }
    __syncthreads();

    // ---- stage fp32 tile (acc/32 + bias) in smem ----
    float* st = (float*)smemb;
    const float inv32 = 1.0f / 32.0f;
    const int qr = lane >> 2, qc = lane & 3;
    #pragma unroll
    for (int im = 0; im < 4; im++) {
        #pragma unroll
        for (int jn = 0; jn < 4; jn++) {
            int rr = wm + im * 16 + qr;
            int cc = wn + jn * 8 + 2 * qc;
            float b0v = bias[col0 + cc], b1v = bias[col0 + cc + 1];
            st[rr * STF + cc]           = acc[im][jn][0] * inv32 + b0v;
            st[rr * STF + cc + 1]       = acc[im][jn][1] * inv32 + b1v;
            st[(rr + 8) * STF + cc]     = acc[im][jn][2] * inv32 + b0v;
            st[(rr + 8) * STF + cc + 1] = acc[im][jn][3] * inv32 + b1v;
        }
    }
    __syncthreads();

    const int tile = col0 >> 7;      // 0-15 q, 16-19 k
    const int bb = row0 >> 11;
    const float scale = 0.08838834764831845f;

    bool isq = tile < 16;
    int hh = isq ? tile : tile - 16;
    int nh = isq ? H : G;
    __nv_bfloat16* dh = isq ? g_qsh : g_ksh;
    __nv_bfloat16* dl = isq ? g_qsl : g_ksl;
    float sc = isq ? scale : 1.0f;
    #pragma unroll 4
    for (int t = 0; t < 16; t++) {
        int idx = tid + t * 256;
        int r = idx >> 5;
        int i2 = (idx & 31) * 2;
        int s = (row0 + r) & (S - 1);
        float a0 = st[r * STF + i2],      a1 = st[r * STF + i2 + 1];
        float c0 = st[r * STF + i2 + 64], c1 = st[r * STF + i2 + 65];
        float4 tcs = *(const float4*)&g_rope[(size_t)s * 64 + i2];
        float o10 = (a0 * tcs.x - c0 * tcs.y) * sc;
        float o11 = (a1 * tcs.z - c1 * tcs.w) * sc;
        float o20 = (c0 * tcs.x + a0 * tcs.y) * sc;
        float o21 = (c1 * tcs.z + a1 * tcs.w) * sc;
        unsigned h1, l1, h2, l2;
        split2(o10, o11, h1, l1);
        split2(o20, o21, h2, l2);
        size_t dst = ((size_t)(bb * nh + hh) * S + s) * HD + i2;
        *(unsigned*)&dh[dst] = h1;
        *(unsigned*)&dl[dst] = l1;
        *(unsigned*)&dh[dst + 64] = h2;
        *(unsigned*)&dl[dst + 64] = l2;
    }
}

// ============== shared fp16 single-term mainloop (3-stage) ===================
#define STH_EL 9472   // per-stage elements: 128*40 + 32*136

__device__ __forceinline__ void gemm_h_mainloop(
    const __half* __restrict__ Ag, const __half* __restrict__ Bg,
    int K, int N, int row0, int col0, unsigned smBase, float (*acc)[4][4]) {
    const int tid = threadIdx.x;
    const int lane = tid & 31;
    const int warp = tid >> 5;
    const int wm = (warp >> 2) * 64;
    const int wn = (warp & 3) * 32;
    const int NT = K / 32;

    auto issue = [&](int st, int k0) {
        unsigned sb = smBase + st * (STH_EL * 2);
        #pragma unroll
        for (int j = 0; j < 2; j++) {
            int c = tid + j * 256;
            int r = c >> 2, c8 = (c & 3) * 8;
            unsigned so = (unsigned)(r * LDA + c8) * 2;
            CP16(sb + so, &Ag[(size_t)(row0 + r) * K + k0 + c8]);
        }
        #pragma unroll
        for (int j = 0; j < 2; j++) {
            int c = tid + j * 256;
            int r = c >> 4, c8 = (c & 15) * 8;
            unsigned so = (unsigned)(r * LDB + c8) * 2;
            CP16(sb + 10240 + so, &Bg[(size_t)(k0 + r) * N + col0 + c8]);
        }
    };

    issue(0, 0);
    CP_COMMIT;
    issue(1, 32);
    CP_COMMIT;

    for (int it = 0; it < NT; it++) {
        if (it == NT - 1) {
            asm volatile("cp.async.wait_group 0;");
        } else {
            asm volatile("cp.async.wait_group 1;");
        }
        __syncthreads();
        if (it + 2 < NT) {
            issue((it + 2) % 3, (it + 2) * 32);
            CP_COMMIT;
        }

        unsigned sb = smBase + (it % 3) * (STH_EL * 2);
        const unsigned aBase = sb;
        const unsigned bBase = sb + 10240;

        #pragma unroll
        for (int ks = 0; ks < 2; ks++) {
            unsigned ah[4][4];
            #pragma unroll
            for (int im = 0; im < 4; im++) {
                unsigned off =
                    ((wm + im * 16 + (lane & 15)) * LDA + ks * 16 + (lane >> 4) * 8) * 2;
                LDSM4(ah[im], aBase + off);
            }
            int krow = ks * 16 + (lane & 7) + ((lane >> 3) & 1) * 8;
            #pragma unroll
            for (int pr = 0; pr < 2; pr++) {
                unsigned bh[4];
                unsigned off = (krow * LDB + wn + pr * 16 + (lane >> 4) * 8) * 2;
                LDSM4T(bh, bBase + off);
                #pragma unroll
                for (int im = 0; im < 4; im++) {
                    MMA16816H(acc[im][pr * 2 + 0], ah[im], bh[0], bh[1]);
                    MMA16816H(acc[im][pr * 2 + 1], ah[im], bh[2], bh[3]);
                }
            }
        }
    }
}

// ============ output projection: A fp16 single x W fp16 single ===============
__global__ __launch_bounds__(256) void gemm_out_h(
    const __half* __restrict__ Ag, const __half* __restrict__ Bg,
    const float* __restrict__ bias, float* __restrict__ C,
    int M, int N, int K) {
    extern __shared__ __nv_bfloat16 smemb[];
    const unsigned smBase = (unsigned)__cvta_generic_to_shared(smemb);

    const int tid = threadIdx.x;
    const int lane = tid & 31;
    const int warp = tid >> 5;
    const int wm = (warp >> 2) * 64;
    const int wn = (warp & 3) * 32;
    const int row0 = blockIdx.y * 128;
    const int col0 = blockIdx.x * 128;

    float acc[4][4][4] = {};
    gemm_h_mainloop(Ag, Bg, K, N, row0, col0, smBase, acc);

    const float inv32 = 1.0f / 32.0f;
    const int qr = lane >> 2, qc = lane & 3;
    #pragma unroll
    for (int im = 0; im < 4; im++) {
        #pragma unroll
        for (int jn = 0; jn < 4; jn++) {
            int row = row0 + wm + im * 16 + qr;
            int col = col0 + wn + jn * 8 + 2 * qc;
            float b0v = bias[col], b1v = bias[col + 1];
            float2 o0 = make_float2(acc[im][jn][0] * inv32 + b0v,
                                    acc[im][jn][1] * inv32 + b1v);
            float2 o1 = make_float2(acc[im][jn][2] * inv32 + b0v,
                                    acc[im][jn][3] * inv32 + b1v);
            *(float2*)&C[(size_t)row * N + col] = o0;
            *(float2*)&C[(size_t)(row + 8) * N + col] = o1;
        }
    }
}

// ======= V projection: x fp16 @ Wv fp16 (1-term), writes g_vsh directly ======
__global__ __launch_bounds__(256) void gemm_v_h(
    const __half* __restrict__ Ag, const __half* __restrict__ Bg,
    const float* __restrict__ bv) {
    extern __shared__ __nv_bfloat16 smemb[];
    const unsigned smBase = (unsigned)__cvta_generic_to_shared(smemb);

    const int tid = threadIdx.x;
    const int lane = tid & 31;
    const int warp = tid >> 5;
    const int wm = (warp >> 2) * 64;
    const int wn = (warp & 3) * 32;
    const int row0 = blockIdx.y * 128;
    const int col0 = blockIdx.x * 128;

    float acc[4][4][4] = {};
    gemm_h_mainloop(Ag, Bg, D, 512, row0, col0, smBase, acc);

    const int gg = col0 >> 7;
    const int qr = lane >> 2, qc = lane & 3;
    #pragma unroll
    for (int im = 0; im < 4; im++) {
        #pragma unroll
        for (int jn = 0; jn < 4; jn++) {
            int row = row0 + wm + im * 16 + qr;
            int hd = wn + jn * 8 + 2 * qc;
            float b0v = bv[col0 + hd], b1v = bv[col0 + hd + 1];
            int s0 = row & (S - 1), bb = row >> 11;
            size_t d0 = ((size_t)(bb * G + gg) * S + s0) * HD + hd;
            *(unsigned*)&g_vsh[d0] = packh2(acc[im][jn][0] + b0v, acc[im][jn][1] + b1v);
            int row1 = row + 8;
            int s1 = row1 & (S - 1), bb1 = row1 >> 11;
            size_t d1 = ((size_t)(bb1 * G + gg) * S + s1) * HD + hd;
            *(unsigned*)&g_vsh[d1] = packh2(acc[im][jn][2] + b0v, acc[im][jn][3] + b1v);
        }
    }
}

// == Flash attention: 128-row q tiles, cp.async double-buffered K/V tiles =====
#define LQ 136
#define FST_B (3 * 64 * LQ * 2)

__global__ __launch_bounds__(256) void flash_tc() {
    extern __shared__ __nv_bfloat16 smb[];
    __nv_bfloat16* Qh = smb;
    __nv_bfloat16* Ql = Qh + 128 * LQ;
    const unsigned smBase = (unsigned)__cvta_generic_to_shared(smb);
    const unsigned kvBase = smBase + 2 * 128 * LQ * 2;

    const int tid  = threadIdx.x;
    const int lane = tid & 31;
    const int warp = tid >> 5;
    const int qtile = gridDim.z - 1 - blockIdx.z;
    const int h  = blockIdx.x;
    const int b  = blockIdx.y;
    const int g  = h / (H / G);
    const int q0 = qtile * 128;
    const int wm = warp * 16;

    const unsigned qBH = smBase;
    const unsigned qBL = smBase + 128 * LQ * 2;

    auto kv_issue = [&](int st, int kt2) {
        int k0 = kt2 * 64;
        unsigned sb = kvBase + st * FST_B;
        #pragma unroll
        for (int it = 0; it < 4; it++) {
            int i4 = tid + it * 256;
            int r  = i4 >> 4;
            int c8 = (i4 & 15) * 8;
            size_t gi = ((size_t)(b * G + g) * S + k0 + r) * HD + c8;
            unsigned so = (unsigned)(r * LQ + c8) * 2;
            CP16(sb + so, g_ksh + gi);
            CP16(sb + 64 * LQ * 2 + so, g_ksl + gi);
            CP16(sb + 128 * LQ * 2 + so, g_vsh + gi);
        }
    };

    kv_issue(0, 0);
    CP_COMMIT;

    #pragma unroll
    for (int it = 0; it < 8; it++) {
        int i4 = tid + it * 256;
        int r  = i4 >> 4;
        int c8 = (i4 & 15) * 8;
        size_t gi = ((size_t)(b * H + h) * S + q0 + r) * HD + c8;
        *(uint4*)&Qh[r * LQ + c8] = *(const uint4*)&g_qsh[gi];
        *(uint4*)&Ql[r * LQ + c8] = *(const uint4*)&g_qsl[gi];
    }

    const int gid = lane >> 2, tig = lane & 3;
    const int row0g = q0 + wm + gid;
    const int row1g = row0g + 8;
    const int wmaxrow = q0 + wm + 15;

    float rm0 = -1e30f, rm1 = -1e30f, rl0 = 0.0f, rl1 = 0.0f;
    float oacc[16][4] = {};

    const int NKT = 2 * qtile + 2;
    for (int kt = 0; kt < NKT; kt++) {
        const int k0 = kt * 64;
        if (kt + 1 < NKT) {
            kv_issue((kt + 1) & 1, kt + 1);
            CP_COMMIT;
            asm volatile("cp.async.wait_group 1;");
        } else {
            asm volatile("cp.async.wait_group 0;");
        }
        __syncthreads();

        unsigned sb = kvBase + (kt & 1) * FST_B;
        const unsigned kBH = sb;
        const unsigned kBL = sb + 64 * LQ * 2;
        const unsigned vBH = sb + 128 * LQ * 2;

        if (k0 <= wmaxrow) {
            float sacc[8][4] = {};
            #pragma unroll
            for (int ks = 0; ks < 8; ks++) {
                unsigned ah[4], al[4];
                unsigned offa = ((wm + (lane & 15)) * LQ + ks * 16 + (lane >> 4) * 8) * 2;
                LDSM4(ah, qBH + offa);
                LDSM4(al, qBL + offa);
                #pragma unroll
                for (int np = 0; np < 2; np++) {
                    unsigned kh0[4], kl0[4], kh1[4], kl1[4];
                    unsigned ob0 = (((2 * np + 0) * 16 + (lane >> 4) * 8 + (lane & 7)) * LQ +
                                    ks * 16 + ((lane >> 3) & 1) * 8) * 2;
                    unsigned ob1 = (((2 * np + 1) * 16 + (lane >> 4) * 8 + (lane & 7)) * LQ +
                                    ks * 16 + ((lane >> 3) & 1) * 8) * 2;
                    LDSM4(kh0, kBH + ob0);
                    LDSM4(kl0, kBL + ob0);
                    LDSM4(kh1, kBH + ob1);
                    LDSM4(kl1, kBL + ob1);
                    MMA16816(sacc[4 * np + 0], ah, kh0[0], kh0[1]);
                    MMA16816(sacc[4 * np + 1], ah, kh0[2], kh0[3]);
                    MMA16816(sacc[4 * np + 2], ah, kh1[0], kh1[1]);
                    MMA16816(sacc[4 * np + 3], ah, kh1[2], kh1[3]);
                    MMA16816(sacc[4 * np + 0], ah, kl0[0], kl0[1]);
                    MMA16816(sacc[4 * np + 1], ah, kl0[2], kl0[3]);
                    MMA16816(sacc[4 * np + 2], ah, kl1[0], kl1[1]);
                    MMA16816(sacc[4 * np + 3], ah, kl1[2], kl1[3]);
                    MMA16816(sacc[4 * np + 0], al, kh0[0], kh0[1]);
                    MMA16816(sacc[4 * np + 1], al, kh0[2], kh0[3]);
                    MMA16816(sacc[4 * np + 2], al, kh1[0], kh1[1]);
                    MMA16816(sacc[4 * np + 3], al, kh1[2], kh1[3]);
                }
            }

            if (k0 + 63 > row0g) {
                #pragma unroll
                for (int nt = 0; nt < 8; nt++) {
                    int colg = k0 + nt * 8 + 2 * tig;
                    if (colg > row0g)     sacc[nt][0] = -1e30f;
                    if (colg + 1 > row0g) sacc[nt][1] = -1e30f;
                    if (colg > row1g)     sacc[nt][2] = -1e30f;
                    if (colg + 1 > row1g) sacc[nt][3] = -1e30f;
                }
            }

            float mx0 = rm0, mx1 = rm1;
            #pragma unroll
            for (int nt = 0; nt < 8; nt++) {
                mx0 = fmaxf(mx0, fmaxf(sacc[nt][0], sacc[nt][1]));
                mx1 = fmaxf(mx1, fmaxf(sacc[nt][2], sacc[nt][3]));
            }
            mx0 = fmaxf(mx0, __shfl_xor_sync(0xffffffff, mx0, 1));
            mx0 = fmaxf(mx0, __shfl_xor_sync(0xffffffff, mx0, 2));
            mx1 = fmaxf(mx1, __shfl_xor_sync(0xffffffff, mx1, 1));
            mx1 = fmaxf(mx1, __shfl_xor_sync(0xffffffff, mx1, 2));
            float sc0 = __expf(rm0 - mx0);
            float sc1 = __expf(rm1 - mx1);
            rm0 = mx0; rm1 = mx1;
            float sum0 = 0.0f, sum1 = 0.0f;
            #pragma unroll
            for (int nt = 0; nt < 8; nt++) {
                sacc[nt][0] = __expf(sacc[nt][0] - mx0);
                sacc[nt][1] = __expf(sacc[nt][1] - mx0);
                sacc[nt][2] = __expf(sacc[nt][2] - mx1);
                sacc[nt][3] = __expf(sacc[nt][3] - mx1);
                sum0 += sacc[nt][0] + sacc[nt][1];
                sum1 += sacc[nt][2] + sacc[nt][3];
            }
            sum0 += __shfl_xor_sync(0xffffffff, sum0, 1);
            sum0 += __shfl_xor_sync(0xffffffff, sum0, 2);
            sum1 += __shfl_xor_sync(0xffffffff, sum1, 1);
            sum1 += __shfl_xor_sync(0xffffffff, sum1, 2);
            rl0 = rl0 * sc0 + sum0;
            rl1 = rl1 * sc1 + sum1;
            #pragma unroll
            for (int nt = 0; nt < 16; nt++) {
                oacc[nt][0] *= sc0; oacc[nt][1] *= sc0;
                oacc[nt][2] *= sc1; oacc[nt][3] *= sc1;
            }

            #pragma unroll
            for (int j = 0; j < 4; j++) {
                unsigned ph[4];
                ph[0] = packh2(sacc[2 * j][0],     sacc[2 * j][1]);
                ph[1] = packh2(sacc[2 * j][2],     sacc[2 * j][3]);
                ph[2] = packh2(sacc[2 * j + 1][0], sacc[2 * j + 1][1]);
                ph[3] = packh2(sacc[2 * j + 1][2], sacc[2 * j + 1][3]);
                #pragma unroll
                for (int nb = 0; nb < 8; nb++) {
                    unsigned vh4[4];
                    unsigned offv = ((j * 16 + (lane & 7) + ((lane >> 3) & 1) * 8) * LQ +
                                     nb * 16 + (lane >> 4) * 8) * 2;
                    LDSM4T(vh4, vBH + offv);
                    MMA16816H(oacc[2 * nb + 0], ph, vh4[0], vh4[1]);
                    MMA16816H(oacc[2 * nb + 1], ph, vh4[2], vh4[3]);
                }
            }
        }
        __syncthreads();
    }

    float li0 = 1.0f / rl0, li1 = 1.0f / rl1;
    size_t or0 = (size_t)(b * S + row0g) * (H * HD) + h * HD;
    size_t or1 = (size_t)(b * S + row1g) * (H * HD) + h * HD;
    #pragma unroll
    for (int nt = 0; nt < 16; nt++) {
        int col = nt * 8 + 2 * tig;
        *(unsigned*)&g_ah[or0 + col] = packh2(oacc[nt][0] * li0, oacc[nt][1] * li0);
        *(unsigned*)&g_ah[or1 + col] = packh2(oacc[nt][2] * li1, oacc[nt][3] * li1);
    }
}

// =============================== launch ======================================
extern "C" void kernel_launch(void* const* d_in, const int* in_sizes, int n_in,
                              void* d_out, int out_size) {
    const float* x  = (const float*)d_in[0];
    const float* Wq = (const float*)d_in[1];
    const float* bq = (const float*)d_in[2];
    const float* Wk = (const float*)d_in[3];
    const float* bk = (const float*)d_in[4];
    const float* Wv = (const float*)d_in[5];
    const float* bv = (const float*)d_in[6];
    const float* Wo = (const float*)d_in[7];
    const float* bo = (const float*)d_in[8];
    float* out = (float*)d_out;

    __half *xf, *wqkh, *wqkl, *wvf, *woh, *ah;
    float *bqkv;
    cudaGetSymbolAddress((void**)&xf, g_xf);
    cudaGetSymbolAddress((void**)&wqkh, g_wqkh);
    cudaGetSymbolAddress((void**)&wqkl, g_wqkl);
    cudaGetSymbolAddress((void**)&wvf, g_wvf);
    cudaGetSymbolAddress((void**)&woh, g_woh);
    cudaGetSymbolAddress((void**)&ah, g_ah);
    cudaGetSymbolAddress((void**)&bqkv, g_bqkv);

    const int M = B * S;  // 8192

    convert_all<<<(CTOT + 255) / 256, 256>>>(x, Wq, Wk, Wv, Wo, bq, bk, bv);

    size_t gsm = (size_t)3 * QK_ST_B;               // 82944 B (2 CTAs/SM)
    cudaFuncSetAttribute(gemm_qk_fused, cudaFuncAttributeMaxDynamicSharedMemorySize, (int)gsm);
    size_t gsmh = (size_t)3 * STH_EL * sizeof(__half);
    cudaFuncSetAttribute(gemm_out_h, cudaFuncAttributeMaxDynamicSharedMemorySize, (int)gsmh);
    cudaFuncSetAttribute(gemm_v_h, cudaFuncAttributeMaxDynamicSharedMemorySize, (int)gsmh);

    // ---- QK projection (2-term fp16, rope/split fused) ----
    gemm_qk_fused<<<dim3(NQK / 128, M / 128), 256, gsm>>>(xf, wqkh, wqkl, bqkv);

    // ---- V projection (1-term fp16) ----
    gemm_v_h<<<dim3(512 / 128, M / 128), 256, gsmh>>>(xf, wvf, bv);

    // ---- flash attention (double-buffered K/V) ----
    size_t smem = (size_t)(2 * 128 * LQ * 2) + 2 * FST_B;
    cudaFuncSetAttribute(flash_tc, cudaFuncAttributeMaxDynamicSharedMemorySize, (int)smem);
    flash_tc<<<dim3(H, B, S / 128), 256, smem>>>();

    // ---- output projection ----
    gemm_out_h<<<dim3(D / 128, M / 128), 256, gsmh>>>(
        ah, woh, bo, out, M, D, H * HD);
}